// round 3
// baseline (speedup 1.0000x reference)
#include <cuda_runtime.h>

#define BB 8
#define NN 2048
#define CC 128
#define KK 512

typedef unsigned long long ull;

// Scratch (device globals: no allocations allowed)
__device__ __align__(16) float g_h[BB * NN * CC];   // 8 MB: h = x@W
__device__ float g_s1[BB * NN];
__device__ float g_s2[BB * NN];
__device__ float g_maxs2[BB];
__device__ float g_hp[BB * CC];          // relu(column-mean of h) per batch
__device__ float g_xpart[BB * 16 * CC];  // partial column sums of x
__device__ int   g_rank[BB * NN];
__device__ int   g_sel[BB * KK];         // ascending selected row ids per batch
__device__ unsigned char g_mask[BB * NN];

__device__ __forceinline__ float lrelu(float v) { return v >= 0.f ? v : 0.01f * v; }

__device__ __forceinline__ ull dupf(float v) {
    ull r;
    asm("mov.b64 %0, {%1, %1};" : "=l"(r) : "f"(v));
    return r;
}

// ---------------------------------------------------------------------------
// Kernel A: h = x @ W. 128 thr = 4 groups x 32 lanes; 8 rows/group, 4 cols/lane.
// Packed f32x2 FMAs; W rows loaded as pre-paired ulonglong2 (no packing needed).
// grid = BB*NN/32 = 512 blocks.
// ---------------------------------------------------------------------------
__global__ void __launch_bounds__(128) k_h(const float* __restrict__ x,
                                           const float* __restrict__ W) {
    __shared__ __align__(16) float xs[32][128];   // 16 KB
    int t = threadIdx.x;
    int g = t >> 5, lane = t & 31;
    long row0 = (long)blockIdx.x * 32;

    const float4* xsrc = (const float4*)(x + row0 * CC);
    float4* xdst = (float4*)xs;
#pragma unroll
    for (int q = 0; q < 8; q++) xdst[t + 128 * q] = xsrc[t + 128 * q];
    __syncthreads();

    ull acc[8][2];
#pragma unroll
    for (int r = 0; r < 8; r++) { acc[r][0] = 0; acc[r][1] = 0; }

    const ulonglong2* Wp = (const ulonglong2*)(W);   // row k: Wp[k*32 + lane]

#pragma unroll 4
    for (int k = 0; k < 128; k += 2) {
        ulonglong2 w0 = Wp[(k + 0) * 32 + lane];
        ulonglong2 w1 = Wp[(k + 1) * 32 + lane];
#pragma unroll
        for (int r = 0; r < 8; r++) {
            float xk0, xk1;
            ull xv = *(const ull*)&xs[g * 8 + r][k];
            asm("mov.b64 {%0, %1}, %2;" : "=f"(xk0), "=f"(xk1) : "l"(xv));
            ull d0 = dupf(xk0), d1 = dupf(xk1);
            asm("fma.rn.f32x2 %0, %1, %2, %0;" : "+l"(acc[r][0]) : "l"(d0), "l"(w0.x));
            asm("fma.rn.f32x2 %0, %1, %2, %0;" : "+l"(acc[r][1]) : "l"(d0), "l"(w0.y));
            asm("fma.rn.f32x2 %0, %1, %2, %0;" : "+l"(acc[r][0]) : "l"(d1), "l"(w1.x));
            asm("fma.rn.f32x2 %0, %1, %2, %0;" : "+l"(acc[r][1]) : "l"(d1), "l"(w1.y));
        }
    }

#pragma unroll
    for (int r = 0; r < 8; r++) {
        ulonglong2 v;
        v.x = acc[r][0];
        v.y = acc[r][1];
        *(ulonglong2*)&g_h[(row0 + g * 8 + r) * CC + 4 * lane] = v;
    }
}

// ---------------------------------------------------------------------------
// Kernel A2: s1 = h@a1, s2 = h@a2 (one warp per row); also zeroes g_rank.
// ---------------------------------------------------------------------------
__global__ void __launch_bounds__(256) k_s(const float* __restrict__ a) {
    int t = threadIdx.x;
    int row = blockIdx.x * 8 + (t >> 5);
    int lane = t & 31;
    const float* hr = g_h + (long)row * CC;
    float p1 = 0.f, p2 = 0.f;
#pragma unroll
    for (int q = 0; q < 4; q++) {
        float hv = hr[lane + 32 * q];
        p1 = fmaf(hv, a[lane + 32 * q], p1);
        p2 = fmaf(hv, a[CC + lane + 32 * q], p2);
    }
#pragma unroll
    for (int o = 16; o; o >>= 1) {
        p1 += __shfl_xor_sync(0xffffffffu, p1, o);
        p2 += __shfl_xor_sync(0xffffffffu, p2, o);
    }
    if (lane == 0) { g_s1[row] = p1; g_s2[row] = p2; g_rank[row] = 0; }
}

// ---------------------------------------------------------------------------
// Kernel X: partial column sums of x (for colmean(h) = colmean(x) @ W).
// ---------------------------------------------------------------------------
__global__ void __launch_bounds__(256) k_xpart(const float* __restrict__ x) {
    int b = blockIdx.y, chunk = blockIdx.x;
    int t = threadIdx.x;
    int c = t & 127, h2 = t >> 7;
    const float* xb = x + ((long)b * NN + chunk * 128) * CC;
    float s = 0.f;
    for (int r = h2; r < 128; r += 2) s += xb[(long)r * CC + c];
    __shared__ float red[256];
    red[t] = s;
    __syncthreads();
    if (h2 == 0) g_xpart[(b * 16 + chunk) * CC + c] = red[c] + red[c + 128];
}

// ---------------------------------------------------------------------------
// Kernel B1: partial rank counting. 2 i-keys per thread.
// grid (4 i-chunks of 512, 8 j-chunks of 256, B). Integer atomics.
// ---------------------------------------------------------------------------
__device__ __forceinline__ ull rankkey(int b, int idx) {
    unsigned u = __float_as_uint(g_s1[b * NN + idx]);
    unsigned key = (u & 0x80000000u) ? ~u : (u | 0x80000000u);
    return ((ull)key << 11) | (unsigned)(NN - 1 - idx);
}

__global__ void __launch_bounds__(256) k_rank() {
    int b = blockIdx.z;
    int t = threadIdx.x;
    __shared__ ull jk[256];
    jk[t] = rankkey(b, blockIdx.y * 256 + t);
    __syncthreads();
    int i0 = blockIdx.x * 512 + t;
    ull me0 = rankkey(b, i0);
    ull me1 = rankkey(b, i0 + 256);
    int c0 = 0, c1 = 0;
#pragma unroll 16
    for (int j = 0; j < 256; j++) {
        ull kj = jk[j];
        c0 += (kj > me0) ? 1 : 0;
        c1 += (kj > me1) ? 1 : 0;
    }
    atomicAdd(&g_rank[b * NN + i0], c0);
    atomicAdd(&g_rank[b * NN + i0 + 256], c1);
}

// ---------------------------------------------------------------------------
// Kernel B2: per batch — mask from ranks, max(s2), ascending compaction,
// and hp = relu((colmean x) @ W).
// ---------------------------------------------------------------------------
__global__ void __launch_bounds__(256) k_prep(const float* __restrict__ W) {
    int b = blockIdx.x;
    int t = threadIdx.x;
    __shared__ float red[256];
    __shared__ int cnts[256];
    __shared__ int offs[256];
    __shared__ float xm[128];

    float m = -3.4e38f;
    for (int idx = t; idx < NN; idx += 256) m = fmaxf(m, g_s2[b * NN + idx]);
    red[t] = m;
    __syncthreads();
    for (int o = 128; o; o >>= 1) {
        if (t < o) red[t] = fmaxf(red[t], red[t + o]);
        __syncthreads();
    }
    if (t == 0) g_maxs2[b] = red[0];

    int base = t * 8;
    unsigned char f[8];
    int c = 0;
#pragma unroll
    for (int r = 0; r < 8; r++) {
        f[r] = (g_rank[b * NN + base + r] < KK) ? 1 : 0;
        g_mask[b * NN + base + r] = f[r];
        c += f[r];
    }
    cnts[t] = c;
    __syncthreads();
    if (t == 0) {
        int s = 0;
        for (int q = 0; q < 256; q++) { offs[q] = s; s += cnts[q]; }
    }
    __syncthreads();
    int pos = offs[t];
#pragma unroll
    for (int r = 0; r < 8; r++)
        if (f[r]) g_sel[b * KK + pos++] = base + r;

    if (t < 128) {
        float s = 0.f;
#pragma unroll
        for (int k = 0; k < 16; k++) s += g_xpart[(b * 16 + k) * CC + t];
        xm[t] = s * (1.0f / NN);
    }
    __syncthreads();
    if (t < 128) {
        float acc = 0.f;
#pragma unroll 8
        for (int k = 0; k < 128; k++) acc = fmaf(xm[k], W[k * CC + t], acc);
        g_hp[b * CC + t] = fmaxf(acc, 0.f);
    }
}

// ---------------------------------------------------------------------------
// Kernel C: attention over the 512 selected rows.
// 128 thr (4 warps), 8 rows/warp, 4 cols/lane, packed f32x2 FMAs.
// cp.async double-buffered 32-j h tiles (2x16KB) + s2 tile (8KB) = 40KB smem.
// grid (16, B) = 128 blocks -> 1 block/SM, single wave.
// ---------------------------------------------------------------------------
__global__ void __launch_bounds__(128) k_attn(float* __restrict__ out) {
    int b = blockIdx.y;
    int t = threadIdx.x, warp = t >> 5, lane = t & 31;
    __shared__ __align__(16) float hs[2][32 * 128];   // 2 x 16 KB
    __shared__ float s2s[NN];                          // 8 KB

    for (int idx = t; idx < NN; idx += 128) s2s[idx] = g_s2[b * NN + idx];

    int slot = blockIdx.x * 32 + warp * 8;
    int rows[8];
    float s1r[8], Mr[8], Z[8];
    float ms2 = g_maxs2[b];
#pragma unroll
    for (int r = 0; r < 8; r++) {
        rows[r] = g_sel[b * KK + slot + r];
        s1r[r] = g_s1[b * NN + rows[r]];
        Mr[r] = lrelu(s1r[r] + ms2);
        Z[r] = 0.f;
    }

    ull acc[8][2];
#pragma unroll
    for (int r = 0; r < 8; r++) { acc[r][0] = 0; acc[r][1] = 0; }

    const float* hb = g_h + (long)b * NN * CC;

    // --- cp.async tile copy: 32 j x 128 c = 16KB, 8 x 16B per thread ---
#define COPY_TILE(buf, jt)                                                        \
    {                                                                             \
        const float4* src = (const float4*)(hb + (long)(jt) * CC);                \
        unsigned dbase = (unsigned)__cvta_generic_to_shared(&hs[buf][0]);         \
        _Pragma("unroll")                                                         \
        for (int q = 0; q < 8; q++) {                                             \
            unsigned da = dbase + (t + 128 * q) * 16;                             \
            asm volatile("cp.async.cg.shared.global [%0], [%1], 16;"              \
                         :: "r"(da), "l"(src + t + 128 * q) : "memory");          \
        }                                                                         \
        asm volatile("cp.async.commit_group;" ::: "memory");                      \
    }

    COPY_TILE(0, 0)

    for (int tile = 0; tile < 64; tile++) {
        if (tile < 63) {
            COPY_TILE((tile + 1) & 1, (tile + 1) * 32)
            asm volatile("cp.async.wait_group 1;" ::: "memory");
        } else {
            asm volatile("cp.async.wait_group 0;" ::: "memory");
        }
        __syncthreads();

        const float* hbuf = hs[tile & 1];
        int jt = tile * 32;

        float v = s2s[jt + lane];
        float w[8];
#pragma unroll
        for (int r = 0; r < 8; r++) {
            float e = s1r[r] + v;
            e = (e >= 0.f) ? e : 0.01f * e;
            w[r] = __expf(e - Mr[r]);
            Z[r] += w[r];
        }

#pragma unroll 8
        for (int tt = 0; tt < 32; tt++) {
            ulonglong2 hv = *(const ulonglong2*)(hbuf + tt * 128 + 4 * lane);
#pragma unroll
            for (int r = 0; r < 8; r++) {
                float wt = __shfl_sync(0xffffffffu, w[r], tt);
                ull wp = dupf(wt);
                asm("fma.rn.f32x2 %0, %1, %2, %0;" : "+l"(acc[r][0]) : "l"(wp), "l"(hv.x));
                asm("fma.rn.f32x2 %0, %1, %2, %0;" : "+l"(acc[r][1]) : "l"(wp), "l"(hv.y));
            }
        }
        __syncthreads();
    }
#undef COPY_TILE

#pragma unroll
    for (int r = 0; r < 8; r++)
#pragma unroll
        for (int o = 16; o; o >>= 1)
            Z[r] += __shfl_xor_sync(0xffffffffu, Z[r], o);

    float* ob = out + (long)b * CC * NN;
#pragma unroll
    for (int r = 0; r < 8; r++) {
        float rinv = 1.f / Z[r];
        int i = rows[r];
        float lo, hi;
        asm("mov.b64 {%0, %1}, %2;" : "=f"(lo), "=f"(hi) : "l"(acc[r][0]));
        ob[(4 * lane + 0) * NN + i] = fmaxf(lo * rinv, 0.f);
        ob[(4 * lane + 1) * NN + i] = fmaxf(hi * rinv, 0.f);
        asm("mov.b64 {%0, %1}, %2;" : "=f"(lo), "=f"(hi) : "l"(acc[r][1]));
        ob[(4 * lane + 2) * NN + i] = fmaxf(lo * rinv, 0.f);
        ob[(4 * lane + 3) * NN + i] = fmaxf(hi * rinv, 0.f);
    }
}

// ---------------------------------------------------------------------------
// Kernel D: masked rows get the shared relu(colmean h) vector.
// ---------------------------------------------------------------------------
__global__ void __launch_bounds__(256) k_fill(float* __restrict__ out) {
    int idx = blockIdx.x * 256 + threadIdx.x;
    int i = idx & (NN - 1);
    int c = (idx >> 11) & (CC - 1);
    int b = idx >> 18;
    if (!g_mask[b * NN + i]) out[idx] = g_hp[b * CC + c];
}

// ---------------------------------------------------------------------------
extern "C" void kernel_launch(void* const* d_in, const int* in_sizes, int n_in,
                              void* d_out, int out_size) {
    // x: 2097152, W: 16384, a: 256, GL: 262144 (unused)
    const float* x = nullptr;
    const float* W = nullptr;
    const float* a = nullptr;
    for (int k = 0; k < n_in; k++) {
        if (in_sizes[k] == BB * NN * CC)      x = (const float*)d_in[k];
        else if (in_sizes[k] == CC * CC)      W = (const float*)d_in[k];
        else if (in_sizes[k] == 2 * CC)       a = (const float*)d_in[k];
    }
    float* out = (float*)d_out;

    k_h    <<<BB * NN / 32, 128>>>(x, W);
    k_xpart<<<dim3(16, BB), 256>>>(x);
    k_s    <<<BB * NN / 8, 256>>>(a);
    k_rank <<<dim3(4, 8, BB), 256>>>();
    k_prep <<<BB, 256>>>(W);
    k_attn <<<dim3(16, BB), 128>>>(out);
    k_fill <<<BB * CC * NN / 256, 256>>>(out);
}

// round 4
// speedup vs baseline: 1.1641x; 1.1641x over previous
#include <cuda_runtime.h>

#define BB 8
#define NN 2048
#define CC 128
#define KK 512

typedef unsigned long long ull;

// Scratch (device globals: no allocations allowed)
__device__ __align__(16) float g_h[BB * NN * CC];   // 8 MB: h = x@W
__device__ float g_s1[BB * NN];
__device__ float g_s2[BB * NN];
__device__ float g_maxs2[BB];
__device__ float g_hp[BB * CC];          // relu(column-mean of h) per batch
__device__ float g_xpart[BB * 16 * CC];  // partial column sums of x
__device__ int   g_rank[BB * NN];
__device__ int   g_sel[BB * KK];         // ascending selected row ids per batch
__device__ unsigned char g_mask[BB * NN];

__device__ __forceinline__ float lrelu(float v) { return v >= 0.f ? v : 0.01f * v; }

__device__ __forceinline__ ull dupf(float v) {
    ull r;
    asm("mov.b64 %0, {%1, %1};" : "=l"(r) : "f"(v));
    return r;
}

// ---------------------------------------------------------------------------
// Kernel A: h = x @ W. 128 thr = 4 groups x 32 lanes; 8 rows/group, 4 cols/lane.
// ---------------------------------------------------------------------------
__global__ void __launch_bounds__(128) k_h(const float* __restrict__ x,
                                           const float* __restrict__ W) {
    __shared__ __align__(16) float xs[32][128];   // 16 KB
    int t = threadIdx.x;
    int g = t >> 5, lane = t & 31;
    long row0 = (long)blockIdx.x * 32;

    const float4* xsrc = (const float4*)(x + row0 * CC);
    float4* xdst = (float4*)xs;
#pragma unroll
    for (int q = 0; q < 8; q++) xdst[t + 128 * q] = xsrc[t + 128 * q];
    __syncthreads();

    ull acc[8][2];
#pragma unroll
    for (int r = 0; r < 8; r++) { acc[r][0] = 0; acc[r][1] = 0; }

    const ulonglong2* Wp = (const ulonglong2*)(W);

#pragma unroll 4
    for (int k = 0; k < 128; k += 2) {
        ulonglong2 w0 = Wp[(k + 0) * 32 + lane];
        ulonglong2 w1 = Wp[(k + 1) * 32 + lane];
#pragma unroll
        for (int r = 0; r < 8; r++) {
            float xk0, xk1;
            ull xv = *(const ull*)&xs[g * 8 + r][k];
            asm("mov.b64 {%0, %1}, %2;" : "=f"(xk0), "=f"(xk1) : "l"(xv));
            ull d0 = dupf(xk0), d1 = dupf(xk1);
            asm("fma.rn.f32x2 %0, %1, %2, %0;" : "+l"(acc[r][0]) : "l"(d0), "l"(w0.x));
            asm("fma.rn.f32x2 %0, %1, %2, %0;" : "+l"(acc[r][1]) : "l"(d0), "l"(w0.y));
            asm("fma.rn.f32x2 %0, %1, %2, %0;" : "+l"(acc[r][0]) : "l"(d1), "l"(w1.x));
            asm("fma.rn.f32x2 %0, %1, %2, %0;" : "+l"(acc[r][1]) : "l"(d1), "l"(w1.y));
        }
    }

#pragma unroll
    for (int r = 0; r < 8; r++) {
        ulonglong2 v;
        v.x = acc[r][0];
        v.y = acc[r][1];
        *(ulonglong2*)&g_h[(row0 + g * 8 + r) * CC + 4 * lane] = v;
    }
}

// ---------------------------------------------------------------------------
// Kernel A2: s1 = h@a1, s2 = h@a2 (one warp per row); also zeroes g_rank.
// ---------------------------------------------------------------------------
__global__ void __launch_bounds__(256) k_s(const float* __restrict__ a) {
    int t = threadIdx.x;
    int row = blockIdx.x * 8 + (t >> 5);
    int lane = t & 31;
    const float* hr = g_h + (long)row * CC;
    float p1 = 0.f, p2 = 0.f;
#pragma unroll
    for (int q = 0; q < 4; q++) {
        float hv = hr[lane + 32 * q];
        p1 = fmaf(hv, a[lane + 32 * q], p1);
        p2 = fmaf(hv, a[CC + lane + 32 * q], p2);
    }
#pragma unroll
    for (int o = 16; o; o >>= 1) {
        p1 += __shfl_xor_sync(0xffffffffu, p1, o);
        p2 += __shfl_xor_sync(0xffffffffu, p2, o);
    }
    if (lane == 0) { g_s1[row] = p1; g_s2[row] = p2; g_rank[row] = 0; }
}

// ---------------------------------------------------------------------------
// Kernel X: partial column sums of x (for colmean(h) = colmean(x) @ W).
// ---------------------------------------------------------------------------
__global__ void __launch_bounds__(256) k_xpart(const float* __restrict__ x) {
    int b = blockIdx.y, chunk = blockIdx.x;
    int t = threadIdx.x;
    int c = t & 127, h2 = t >> 7;
    const float* xb = x + ((long)b * NN + chunk * 128) * CC;
    float s = 0.f;
    for (int r = h2; r < 128; r += 2) s += xb[(long)r * CC + c];
    __shared__ float red[256];
    red[t] = s;
    __syncthreads();
    if (h2 == 0) g_xpart[(b * 16 + chunk) * CC + c] = red[c] + red[c + 128];
}

// ---------------------------------------------------------------------------
// Kernel B1: partial rank counting. 2 i-keys per thread.
// ---------------------------------------------------------------------------
__device__ __forceinline__ ull rankkey(int b, int idx) {
    unsigned u = __float_as_uint(g_s1[b * NN + idx]);
    unsigned key = (u & 0x80000000u) ? ~u : (u | 0x80000000u);
    return ((ull)key << 11) | (unsigned)(NN - 1 - idx);
}

__global__ void __launch_bounds__(256) k_rank() {
    int b = blockIdx.z;
    int t = threadIdx.x;
    __shared__ ull jk[256];
    jk[t] = rankkey(b, blockIdx.y * 256 + t);
    __syncthreads();
    int i0 = blockIdx.x * 512 + t;
    ull me0 = rankkey(b, i0);
    ull me1 = rankkey(b, i0 + 256);
    int c0 = 0, c1 = 0;
#pragma unroll 16
    for (int j = 0; j < 256; j++) {
        ull kj = jk[j];
        c0 += (kj > me0) ? 1 : 0;
        c1 += (kj > me1) ? 1 : 0;
    }
    atomicAdd(&g_rank[b * NN + i0], c0);
    atomicAdd(&g_rank[b * NN + i0 + 256], c1);
}

// ---------------------------------------------------------------------------
// Kernel B2: mask from ranks, max(s2), compaction, hp = relu((colmean x)@W).
// ---------------------------------------------------------------------------
__global__ void __launch_bounds__(256) k_prep(const float* __restrict__ W) {
    int b = blockIdx.x;
    int t = threadIdx.x;
    __shared__ float red[256];
    __shared__ int cnts[256];
    __shared__ int offs[256];
    __shared__ float xm[128];

    float m = -3.4e38f;
    for (int idx = t; idx < NN; idx += 256) m = fmaxf(m, g_s2[b * NN + idx]);
    red[t] = m;
    __syncthreads();
    for (int o = 128; o; o >>= 1) {
        if (t < o) red[t] = fmaxf(red[t], red[t + o]);
        __syncthreads();
    }
    if (t == 0) g_maxs2[b] = red[0];

    int base = t * 8;
    unsigned char f[8];
    int c = 0;
#pragma unroll
    for (int r = 0; r < 8; r++) {
        f[r] = (g_rank[b * NN + base + r] < KK) ? 1 : 0;
        g_mask[b * NN + base + r] = f[r];
        c += f[r];
    }
    cnts[t] = c;
    __syncthreads();
    if (t == 0) {
        int s = 0;
        for (int q = 0; q < 256; q++) { offs[q] = s; s += cnts[q]; }
    }
    __syncthreads();
    int pos = offs[t];
#pragma unroll
    for (int r = 0; r < 8; r++)
        if (f[r]) g_sel[b * KK + pos++] = base + r;

    if (t < 128) {
        float s = 0.f;
#pragma unroll
        for (int k = 0; k < 16; k++) s += g_xpart[(b * 16 + k) * CC + t];
        xm[t] = s * (1.0f / NN);
    }
    __syncthreads();
    if (t < 128) {
        float acc = 0.f;
#pragma unroll 8
        for (int k = 0; k < 128; k++) acc = fmaf(xm[k], W[k * CC + t], acc);
        g_hp[b * CC + t] = fmaxf(acc, 0.f);
    }
}

// ---------------------------------------------------------------------------
// Kernel C: attention over the 512 selected rows.
// 128 thr (4 warps), 8 rows/warp, 4 cols/lane.
// Weight broadcast via smem (pre-duplicated f32x2 pairs, LDS.128 broadcast) —
// NO shuffles, NO dup-MOVs in the inner loop.
// cp.async double-buffered 32-j h tiles. grid (16, B) = 128 blocks.
// ---------------------------------------------------------------------------
__global__ void __launch_bounds__(128) k_attn(float* __restrict__ out) {
    int b = blockIdx.y;
    int t = threadIdx.x, warp = t >> 5, lane = t & 31;
    __shared__ __align__(16) float hs[2][32 * 128];        // 2 x 16 KB
    __shared__ __align__(16) ulonglong2 wbuf[4][32][4];    // 8 KB (warp-private)
    __shared__ float s2s[NN];                              // 8 KB

    for (int idx = t; idx < NN; idx += 128) s2s[idx] = g_s2[b * NN + idx];

    int slot = blockIdx.x * 32 + warp * 8;
    int rows[8];
    float s1r[8], Mr[8], Z[8];
    float ms2 = g_maxs2[b];
#pragma unroll
    for (int r = 0; r < 8; r++) {
        rows[r] = g_sel[b * KK + slot + r];
        s1r[r] = g_s1[b * NN + rows[r]];
        Mr[r] = lrelu(s1r[r] + ms2);
        Z[r] = 0.f;
    }

    ull acc[8][2];
#pragma unroll
    for (int r = 0; r < 8; r++) { acc[r][0] = 0; acc[r][1] = 0; }

    const float* hb = g_h + (long)b * NN * CC;

#define COPY_TILE(buf, jt)                                                        \
    {                                                                             \
        const float4* src = (const float4*)(hb + (long)(jt) * CC);                \
        unsigned dbase = (unsigned)__cvta_generic_to_shared(&hs[buf][0]);         \
        _Pragma("unroll")                                                         \
        for (int q = 0; q < 8; q++) {                                             \
            unsigned da = dbase + (t + 128 * q) * 16;                             \
            asm volatile("cp.async.cg.shared.global [%0], [%1], 16;"              \
                         :: "r"(da), "l"(src + t + 128 * q) : "memory");          \
        }                                                                         \
        asm volatile("cp.async.commit_group;" ::: "memory");                      \
    }

    COPY_TILE(0, 0)

    for (int tile = 0; tile < 64; tile++) {
        // weights for this tile: lane covers j = tile*32 + lane, all 8 rows
        float v = s2s[tile * 32 + lane];
        float w[8];
#pragma unroll
        for (int r = 0; r < 8; r++) {
            float e = s1r[r] + v;
            e = (e >= 0.f) ? e : 0.01f * e;
            w[r] = __expf(e - Mr[r]);
            Z[r] += w[r];
        }
#pragma unroll
        for (int p = 0; p < 4; p++) {
            ulonglong2 pk;
            pk.x = dupf(w[2 * p]);
            pk.y = dupf(w[2 * p + 1]);
            wbuf[warp][lane][p] = pk;
        }
        __syncwarp();

        if (tile < 63) {
            COPY_TILE((tile + 1) & 1, (tile + 1) * 32)
            asm volatile("cp.async.wait_group 1;" ::: "memory");
        } else {
            asm volatile("cp.async.wait_group 0;" ::: "memory");
        }
        __syncthreads();

        const float* hbuf = hs[tile & 1];

#pragma unroll 4
        for (int tt = 0; tt < 32; tt++) {
            ulonglong2 hv = *(const ulonglong2*)(hbuf + tt * 128 + 4 * lane);
#pragma unroll
            for (int p = 0; p < 4; p++) {
                ulonglong2 wp = wbuf[warp][tt][p];   // broadcast LDS.128
                asm("fma.rn.f32x2 %0, %1, %2, %0;" : "+l"(acc[2*p  ][0]) : "l"(wp.x), "l"(hv.x));
                asm("fma.rn.f32x2 %0, %1, %2, %0;" : "+l"(acc[2*p  ][1]) : "l"(wp.x), "l"(hv.y));
                asm("fma.rn.f32x2 %0, %1, %2, %0;" : "+l"(acc[2*p+1][0]) : "l"(wp.y), "l"(hv.x));
                asm("fma.rn.f32x2 %0, %1, %2, %0;" : "+l"(acc[2*p+1][1]) : "l"(wp.y), "l"(hv.y));
            }
        }
        __syncthreads();
    }
#undef COPY_TILE

#pragma unroll
    for (int r = 0; r < 8; r++)
#pragma unroll
        for (int o = 16; o; o >>= 1)
            Z[r] += __shfl_xor_sync(0xffffffffu, Z[r], o);

    float* ob = out + (long)b * CC * NN;
#pragma unroll
    for (int r = 0; r < 8; r++) {
        float rinv = 1.f / Z[r];
        int i = rows[r];
        float lo, hi;
        asm("mov.b64 {%0, %1}, %2;" : "=f"(lo), "=f"(hi) : "l"(acc[r][0]));
        ob[(4 * lane + 0) * NN + i] = fmaxf(lo * rinv, 0.f);
        ob[(4 * lane + 1) * NN + i] = fmaxf(hi * rinv, 0.f);
        asm("mov.b64 {%0, %1}, %2;" : "=f"(lo), "=f"(hi) : "l"(acc[r][1]));
        ob[(4 * lane + 2) * NN + i] = fmaxf(lo * rinv, 0.f);
        ob[(4 * lane + 3) * NN + i] = fmaxf(hi * rinv, 0.f);
    }
}

// ---------------------------------------------------------------------------
// Kernel D: masked rows get the shared relu(colmean h) vector.
// ---------------------------------------------------------------------------
__global__ void __launch_bounds__(256) k_fill(float* __restrict__ out) {
    int idx = blockIdx.x * 256 + threadIdx.x;
    int i = idx & (NN - 1);
    int c = (idx >> 11) & (CC - 1);
    int b = idx >> 18;
    if (!g_mask[b * NN + i]) out[idx] = g_hp[b * CC + c];
}

// ---------------------------------------------------------------------------
extern "C" void kernel_launch(void* const* d_in, const int* in_sizes, int n_in,
                              void* d_out, int out_size) {
    const float* x = nullptr;
    const float* W = nullptr;
    const float* a = nullptr;
    for (int k = 0; k < n_in; k++) {
        if (in_sizes[k] == BB * NN * CC)      x = (const float*)d_in[k];
        else if (in_sizes[k] == CC * CC)      W = (const float*)d_in[k];
        else if (in_sizes[k] == 2 * CC)       a = (const float*)d_in[k];
    }
    float* out = (float*)d_out;

    k_h    <<<BB * NN / 32, 128>>>(x, W);
    k_xpart<<<dim3(16, BB), 256>>>(x);
    k_s    <<<BB * NN / 8, 256>>>(a);
    k_rank <<<dim3(4, 8, BB), 256>>>();
    k_prep <<<BB, 256>>>(W);
    k_attn <<<dim3(16, BB), 128>>>(out);
    k_fill <<<BB * CC * NN / 256, 256>>>(out);
}

// round 6
// speedup vs baseline: 1.4982x; 1.2870x over previous
#include <cuda_runtime.h>
#include <cuda_bf16.h>

#define BB 8
#define NN 2048
#define CC 128
#define KK 512

typedef unsigned long long ull;
typedef unsigned int uint;

// ---------------- device scratch (no allocations allowed) ----------------
__device__ __align__(16) float g_h[BB * NN * CC];   // 8 MB fp32 h = x@W
__device__ float g_s1[BB * NN];
__device__ float g_s2[BB * NN];
__device__ float g_maxs2[BB];
__device__ float g_hp[BB * CC];
__device__ float g_xpart[BB * 16 * CC];
__device__ float g_Z[BB * KK];
__device__ int   g_rank[BB * NN];
__device__ int   g_sel[BB * KK];
__device__ unsigned char g_mask[BB * NN];
// split-bf16 operands for the tensor GEMM
__device__ __align__(16) __nv_bfloat16 g_Phi[(long)BB * KK * NN];  // [b][slot][j]
__device__ __align__(16) __nv_bfloat16 g_Plo[(long)BB * KK * NN];
__device__ __align__(16) __nv_bfloat16 g_Bhi[(long)BB * CC * NN];  // [b][c][j]
__device__ __align__(16) __nv_bfloat16 g_Blo[(long)BB * CC * NN];

__device__ __forceinline__ float lrelu(float v) { return v >= 0.f ? v : 0.01f * v; }

__device__ __forceinline__ ull dupf(float v) {
    ull r; asm("mov.b64 %0, {%1, %1};" : "=l"(r) : "f"(v)); return r;
}

// ---------------------------------------------------------------------------
// k_h: h = x@W (fp32, packed f32x2)
// ---------------------------------------------------------------------------
__global__ void __launch_bounds__(128) k_h(const float* __restrict__ x,
                                           const float* __restrict__ W) {
    __shared__ __align__(16) float xs[32][128];
    int t = threadIdx.x;
    int g = t >> 5, lane = t & 31;
    long row0 = (long)blockIdx.x * 32;

    const float4* xsrc = (const float4*)(x + row0 * CC);
    float4* xdst = (float4*)xs;
#pragma unroll
    for (int q = 0; q < 8; q++) xdst[t + 128 * q] = xsrc[t + 128 * q];
    __syncthreads();

    ull acc[8][2];
#pragma unroll
    for (int r = 0; r < 8; r++) { acc[r][0] = 0; acc[r][1] = 0; }
    const ulonglong2* Wp = (const ulonglong2*)(W);

#pragma unroll 4
    for (int k = 0; k < 128; k += 2) {
        ulonglong2 w0 = Wp[(k + 0) * 32 + lane];
        ulonglong2 w1 = Wp[(k + 1) * 32 + lane];
#pragma unroll
        for (int r = 0; r < 8; r++) {
            float xk0, xk1;
            ull xv = *(const ull*)&xs[g * 8 + r][k];
            asm("mov.b64 {%0, %1}, %2;" : "=f"(xk0), "=f"(xk1) : "l"(xv));
            ull d0 = dupf(xk0), d1 = dupf(xk1);
            asm("fma.rn.f32x2 %0, %1, %2, %0;" : "+l"(acc[r][0]) : "l"(d0), "l"(w0.x));
            asm("fma.rn.f32x2 %0, %1, %2, %0;" : "+l"(acc[r][1]) : "l"(d0), "l"(w0.y));
            asm("fma.rn.f32x2 %0, %1, %2, %0;" : "+l"(acc[r][0]) : "l"(d1), "l"(w1.x));
            asm("fma.rn.f32x2 %0, %1, %2, %0;" : "+l"(acc[r][1]) : "l"(d1), "l"(w1.y));
        }
    }
#pragma unroll
    for (int r = 0; r < 8; r++) {
        ulonglong2 v; v.x = acc[r][0]; v.y = acc[r][1];
        *(ulonglong2*)&g_h[(row0 + g * 8 + r) * CC + 4 * lane] = v;
    }
}

// ---------------------------------------------------------------------------
// k_s: s1 = h@a1, s2 = h@a2; zero g_rank
// ---------------------------------------------------------------------------
__global__ void __launch_bounds__(256) k_s(const float* __restrict__ a) {
    int t = threadIdx.x;
    int row = blockIdx.x * 8 + (t >> 5);
    int lane = t & 31;
    const float* hr = g_h + (long)row * CC;
    float p1 = 0.f, p2 = 0.f;
#pragma unroll
    for (int q = 0; q < 4; q++) {
        float hv = hr[lane + 32 * q];
        p1 = fmaf(hv, a[lane + 32 * q], p1);
        p2 = fmaf(hv, a[CC + lane + 32 * q], p2);
    }
#pragma unroll
    for (int o = 16; o; o >>= 1) {
        p1 += __shfl_xor_sync(0xffffffffu, p1, o);
        p2 += __shfl_xor_sync(0xffffffffu, p2, o);
    }
    if (lane == 0) { g_s1[row] = p1; g_s2[row] = p2; g_rank[row] = 0; }
}

// ---------------------------------------------------------------------------
// k_xpart: partial column sums of x
// ---------------------------------------------------------------------------
__global__ void __launch_bounds__(256) k_xpart(const float* __restrict__ x) {
    int b = blockIdx.y, chunk = blockIdx.x;
    int t = threadIdx.x;
    int c = t & 127, h2 = t >> 7;
    const float* xb = x + ((long)b * NN + chunk * 128) * CC;
    float s = 0.f;
    for (int r = h2; r < 128; r += 2) s += xb[(long)r * CC + c];
    __shared__ float red[256];
    red[t] = s;
    __syncthreads();
    if (h2 == 0) g_xpart[(b * 16 + chunk) * CC + c] = red[c] + red[c + 128];
}

// ---------------------------------------------------------------------------
// k_ht: transpose h -> split bf16, layout [b][c][j]
// ---------------------------------------------------------------------------
__global__ void __launch_bounds__(256) k_ht() {
    int b = blockIdx.y, j0 = blockIdx.x * 64;
    int t = threadIdx.x;
    __shared__ float tile[64][132];
    int c = t & 127, jh2 = t >> 7;
#pragma unroll 8
    for (int it = 0; it < 32; it++) {
        int jj = jh2 + 2 * it;
        tile[jj][c] = g_h[((long)b * NN + j0 + jj) * CC + c];
    }
    __syncthreads();
    int co = t >> 1, jhalf = t & 1;
    uint* Bhi = (uint*)g_Bhi;
    uint* Blo = (uint*)g_Blo;
    long rowbase = ((long)b * CC + co) * NN + j0;
#pragma unroll
    for (int q = 0; q < 16; q++) {
        int jj = jhalf * 32 + q * 2;
        float v0 = tile[jj][co], v1 = tile[jj + 1][co];
        __nv_bfloat16 h0 = __float2bfloat16(v0);
        __nv_bfloat16 h1 = __float2bfloat16(v1);
        __nv_bfloat16 l0 = __float2bfloat16(v0 - __bfloat162float(h0));
        __nv_bfloat16 l1 = __float2bfloat16(v1 - __bfloat162float(h1));
        __nv_bfloat162 hp; hp.x = h0; hp.y = h1;
        __nv_bfloat162 lp; lp.x = l0; lp.y = l1;
        Bhi[(rowbase + jj) >> 1] = *(uint*)&hp;
        Blo[(rowbase + jj) >> 1] = *(uint*)&lp;
    }
}

// ---------------------------------------------------------------------------
// k_rank: exact top-512 membership by rank counting
// ---------------------------------------------------------------------------
__device__ __forceinline__ ull rankkey(int b, int idx) {
    unsigned u = __float_as_uint(g_s1[b * NN + idx]);
    unsigned key = (u & 0x80000000u) ? ~u : (u | 0x80000000u);
    return ((ull)key << 11) | (unsigned)(NN - 1 - idx);
}

__global__ void __launch_bounds__(256) k_rank() {
    int b = blockIdx.z;
    int t = threadIdx.x;
    __shared__ ull jk[256];
    jk[t] = rankkey(b, blockIdx.y * 256 + t);
    __syncthreads();
    int i0 = blockIdx.x * 512 + t;
    ull me0 = rankkey(b, i0);
    ull me1 = rankkey(b, i0 + 256);
    int c0 = 0, c1 = 0;
#pragma unroll 16
    for (int j = 0; j < 256; j++) {
        ull kj = jk[j];
        c0 += (kj > me0) ? 1 : 0;
        c1 += (kj > me1) ? 1 : 0;
    }
    atomicAdd(&g_rank[b * NN + i0], c0);
    atomicAdd(&g_rank[b * NN + i0 + 256], c1);
}

// ---------------------------------------------------------------------------
// k_prep: mask, max(s2), compaction, hp = relu((colmean x)@W)
// ---------------------------------------------------------------------------
__global__ void __launch_bounds__(256) k_prep(const float* __restrict__ W) {
    int b = blockIdx.x;
    int t = threadIdx.x;
    __shared__ float red[256];
    __shared__ int cnts[256];
    __shared__ int offs[256];
    __shared__ float xm[128];

    float m = -3.4e38f;
    for (int idx = t; idx < NN; idx += 256) m = fmaxf(m, g_s2[b * NN + idx]);
    red[t] = m;
    __syncthreads();
    for (int o = 128; o; o >>= 1) {
        if (t < o) red[t] = fmaxf(red[t], red[t + o]);
        __syncthreads();
    }
    if (t == 0) g_maxs2[b] = red[0];

    int base = t * 8;
    unsigned char f[8];
    int c = 0;
#pragma unroll
    for (int r = 0; r < 8; r++) {
        f[r] = (g_rank[b * NN + base + r] < KK) ? 1 : 0;
        g_mask[b * NN + base + r] = f[r];
        c += f[r];
    }
    cnts[t] = c;
    __syncthreads();
    if (t == 0) {
        int s = 0;
        for (int q = 0; q < 256; q++) { offs[q] = s; s += cnts[q]; }
    }
    __syncthreads();
    int pos = offs[t];
#pragma unroll
    for (int r = 0; r < 8; r++)
        if (f[r]) g_sel[b * KK + pos++] = base + r;

    if (t < 128) {
        float s = 0.f;
#pragma unroll
        for (int k = 0; k < 16; k++) s += g_xpart[(b * 16 + k) * CC + t];
        xm[t] = s * (1.0f / NN);
    }
    __syncthreads();
    if (t < 128) {
        float acc = 0.f;
#pragma unroll 8
        for (int k = 0; k < 128; k++) acc = fmaf(xm[k], W[k * CC + t], acc);
        g_hp[b * CC + t] = fmaxf(acc, 0.f);
    }
}

// ---------------------------------------------------------------------------
// k_P: materialize P (softmax numerators) as split bf16 + row sums Z.
// ---------------------------------------------------------------------------
__global__ void __launch_bounds__(256) k_P() {
    int b = blockIdx.y;
    int t = threadIdx.x, warp = t >> 5, lane = t & 31;
    int slot = blockIdx.x * 8 + warp;
    int i = g_sel[b * KK + slot];
    float s1 = g_s1[b * NN + i];
    float M = lrelu(s1 + g_maxs2[b]);
    const float* s2b = g_s2 + b * NN;
    uint* Phi = (uint*)g_Phi;
    uint* Plo = (uint*)g_Plo;
    long rowbase = ((long)b * KK + slot) * NN;

    float z = 0.f;
#pragma unroll 4
    for (int q = 0; q < 32; q++) {
        int j0 = 2 * lane + 64 * q;
        float w0 = __expf(lrelu(s1 + s2b[j0]) - M);
        float w1 = __expf(lrelu(s1 + s2b[j0 + 1]) - M);
        z += w0 + w1;
        __nv_bfloat16 h0 = __float2bfloat16(w0);
        __nv_bfloat16 h1 = __float2bfloat16(w1);
        __nv_bfloat16 l0 = __float2bfloat16(w0 - __bfloat162float(h0));
        __nv_bfloat16 l1 = __float2bfloat16(w1 - __bfloat162float(h1));
        __nv_bfloat162 hp; hp.x = h0; hp.y = h1;
        __nv_bfloat162 lp; lp.x = l0; lp.y = l1;
        Phi[(rowbase + j0) >> 1] = *(uint*)&hp;
        Plo[(rowbase + j0) >> 1] = *(uint*)&lp;
    }
#pragma unroll
    for (int o = 16; o; o >>= 1) z += __shfl_xor_sync(0xffffffffu, z, o);
    if (lane == 0) g_Z[b * KK + slot] = z;
}

// ---------------------------------------------------------------------------
// k_gemm: D = P @ h via mma.sync bf16 (3 split passes), fp32 accumulate.
// grid (16 = 8 Mtiles x 2 Ntiles, B), 256 thr (8 warps: 2m x 4n, 32Mx16N each).
// Tile: 64M x 64N, K chunks of 64, cp.async double buffer.
// Smem pitch 72 bf16 -> conflict-free direct LDS fragment loads.
// ---------------------------------------------------------------------------
#define PITCH 72
#define STG_ELEMS (4 * 64 * PITCH)          // Ahi,Alo,Bhi,Blo: 4 x 64 x 72 bf16
#define GEMM_SMEM (2 * STG_ELEMS * 2)       // 73728 bytes

__device__ __forceinline__ void mma_bf16(float* d, const uint* a, const uint* bfr) {
    asm("mma.sync.aligned.m16n8k16.row.col.f32.bf16.bf16.f32 "
        "{%0,%1,%2,%3}, {%4,%5,%6,%7}, {%8,%9}, {%0,%1,%2,%3};"
        : "+f"(d[0]), "+f"(d[1]), "+f"(d[2]), "+f"(d[3])
        : "r"(a[0]), "r"(a[1]), "r"(a[2]), "r"(a[3]), "r"(bfr[0]), "r"(bfr[1]));
}

__global__ void __launch_bounds__(256) k_gemm(float* __restrict__ out) {
    extern __shared__ __align__(16) __nv_bfloat16 S[];
    int t = threadIdx.x, warp = t >> 5, lane = t & 31;
    int g = lane >> 2, tig = lane & 3;
    int wm = warp >> 2, wn = warp & 3;           // 2 x 4 warp grid
    int mt = blockIdx.x & 7, nt = blockIdx.x >> 3, b = blockIdx.y;

    const __nv_bfloat16* srcs[4] = {
        g_Phi + ((long)b * KK + mt * 64) * NN,
        g_Plo + ((long)b * KK + mt * 64) * NN,
        g_Bhi + ((long)b * CC + nt * 64) * NN,
        g_Blo + ((long)b * CC + nt * 64) * NN
    };

#define COPY(buf, chunk)                                                          \
    {                                                                             \
        _Pragma("unroll")                                                         \
        for (int arr = 0; arr < 4; arr++) {                                       \
            const __nv_bfloat16* sp = srcs[arr] + (chunk) * 64;                   \
            uint dbase = (uint)__cvta_generic_to_shared(                          \
                S + (buf) * STG_ELEMS + arr * 64 * PITCH);                        \
            _Pragma("unroll")                                                     \
            for (int q = 0; q < 2; q++) {                                         \
                int idx = t + 256 * q;                                            \
                int row = idx >> 3, seg = idx & 7;                                \
                asm volatile("cp.async.cg.shared.global [%0], [%1], 16;"          \
                             :: "r"(dbase + (row * PITCH + seg * 8) * 2),         \
                                "l"(sp + (long)row * NN + seg * 8) : "memory");   \
            }                                                                     \
        }                                                                         \
        asm volatile("cp.async.commit_group;" ::: "memory");                      \
    }

    float acc[2][2][4];
#pragma unroll
    for (int fm = 0; fm < 2; fm++)
#pragma unroll
        for (int fn = 0; fn < 2; fn++)
#pragma unroll
            for (int q = 0; q < 4; q++) acc[fm][fn][q] = 0.f;

    COPY(0, 0)

    for (int c = 0; c < 32; c++) {
        if (c + 1 < 32) {
            COPY((c + 1) & 1, c + 1)
            asm volatile("cp.async.wait_group 1;" ::: "memory");
        } else {
            asm volatile("cp.async.wait_group 0;" ::: "memory");
        }
        __syncthreads();

        const __nv_bfloat16* Sb = S + (c & 1) * STG_ELEMS;
        const __nv_bfloat16* Ahi = Sb;
        const __nv_bfloat16* Alo = Sb + 64 * PITCH;
        const __nv_bfloat16* Bhi = Sb + 2 * 64 * PITCH;
        const __nv_bfloat16* Blo = Sb + 3 * 64 * PITCH;

#pragma unroll
        for (int ks = 0; ks < 4; ks++) {
            int k0 = ks * 16;
            uint ahi[2][4], alo[2][4], bhi[2][2], blo[2][2];
#pragma unroll
            for (int fm = 0; fm < 2; fm++) {
                int r0 = wm * 32 + fm * 16 + g;
                const uint* pa0 = (const uint*)(Ahi + r0 * PITCH + k0);
                const uint* pa1 = (const uint*)(Ahi + (r0 + 8) * PITCH + k0);
                ahi[fm][0] = pa0[tig]; ahi[fm][1] = pa1[tig];
                ahi[fm][2] = pa0[tig + 4]; ahi[fm][3] = pa1[tig + 4];
                const uint* qa0 = (const uint*)(Alo + r0 * PITCH + k0);
                const uint* qa1 = (const uint*)(Alo + (r0 + 8) * PITCH + k0);
                alo[fm][0] = qa0[tig]; alo[fm][1] = qa1[tig];
                alo[fm][2] = qa0[tig + 4]; alo[fm][3] = qa1[tig + 4];
            }
#pragma unroll
            for (int fn = 0; fn < 2; fn++) {
                int n0 = wn * 16 + fn * 8 + g;
                const uint* pb = (const uint*)(Bhi + n0 * PITCH + k0);
                bhi[fn][0] = pb[tig]; bhi[fn][1] = pb[tig + 4];
                const uint* qb = (const uint*)(Blo + n0 * PITCH + k0);
                blo[fn][0] = qb[tig]; blo[fn][1] = qb[tig + 4];
            }
#pragma unroll
            for (int fm = 0; fm < 2; fm++)
#pragma unroll
                for (int fn = 0; fn < 2; fn++) {
                    mma_bf16(acc[fm][fn], ahi[fm], bhi[fn]);
                    mma_bf16(acc[fm][fn], ahi[fm], blo[fn]);
                    mma_bf16(acc[fm][fn], alo[fm], bhi[fn]);
                }
        }
        __syncthreads();
    }
#undef COPY

    float* ob = out + (long)b * CC * NN;
#pragma unroll
    for (int fm = 0; fm < 2; fm++) {
        int slot0 = mt * 64 + wm * 32 + fm * 16 + g;
        int i0 = g_sel[b * KK + slot0];
        int i1 = g_sel[b * KK + slot0 + 8];
        float z0 = 1.f / g_Z[b * KK + slot0];
        float z1 = 1.f / g_Z[b * KK + slot0 + 8];
#pragma unroll
        for (int fn = 0; fn < 2; fn++) {
            int c0 = nt * 64 + wn * 16 + fn * 8 + 2 * tig;
            ob[(long)(c0)     * NN + i0] = fmaxf(acc[fm][fn][0] * z0, 0.f);
            ob[(long)(c0 + 1) * NN + i0] = fmaxf(acc[fm][fn][1] * z0, 0.f);
            ob[(long)(c0)     * NN + i1] = fmaxf(acc[fm][fn][2] * z1, 0.f);
            ob[(long)(c0 + 1) * NN + i1] = fmaxf(acc[fm][fn][3] * z1, 0.f);
        }
    }
}

// ---------------------------------------------------------------------------
// k_fill: masked rows get the shared relu(colmean h) vector.
// ---------------------------------------------------------------------------
__global__ void __launch_bounds__(256) k_fill(float* __restrict__ out) {
    int idx = blockIdx.x * 256 + threadIdx.x;
    int i = idx & (NN - 1);
    int c = (idx >> 11) & (CC - 1);
    int b = idx >> 18;
    if (!g_mask[b * NN + i]) out[idx] = g_hp[b * CC + c];
}

// ---------------------------------------------------------------------------
extern "C" void kernel_launch(void* const* d_in, const int* in_sizes, int n_in,
                              void* d_out, int out_size) {
    const float* x = nullptr;
    const float* W = nullptr;
    const float* a = nullptr;
    for (int k = 0; k < n_in; k++) {
        if (in_sizes[k] == BB * NN * CC)      x = (const float*)d_in[k];
        else if (in_sizes[k] == CC * CC)      W = (const float*)d_in[k];
        else if (in_sizes[k] == 2 * CC)       a = (const float*)d_in[k];
    }
    float* out = (float*)d_out;

    static int smem_set = 0;
    if (!smem_set) {
        cudaFuncSetAttribute(k_gemm, cudaFuncAttributeMaxDynamicSharedMemorySize, GEMM_SMEM);
        smem_set = 1;
    }

    k_h    <<<BB * NN / 32, 128>>>(x, W);
    k_xpart<<<dim3(16, BB), 256>>>(x);
    k_s    <<<BB * NN / 8, 256>>>(a);
    k_ht   <<<dim3(32, BB), 256>>>();
    k_rank <<<dim3(4, 8, BB), 256>>>();
    k_prep <<<BB, 256>>>(W);
    k_P    <<<dim3(64, BB), 256>>>();
    k_gemm <<<dim3(16, BB), 256, GEMM_SMEM>>>(out);
    k_fill <<<BB * CC * NN / 256, 256>>>(out);
}

// round 7
// speedup vs baseline: 1.7825x; 1.1897x over previous
#include <cuda_runtime.h>
#include <cuda_bf16.h>

#define BB 8
#define NN 2048
#define CC 128
#define KK 512

typedef unsigned long long ull;
typedef unsigned int uint;

// ---------------- device scratch (no allocations allowed) ----------------
__device__ float g_s1[BB * NN];
__device__ float g_s2[BB * NN];
__device__ float g_maxs2[BB];
__device__ float g_hp[BB * CC];
__device__ float g_xpart[512 * CC];      // per-k_h-block column partial sums of x
__device__ float g_Z[BB * KK];
__device__ int   g_rank[BB * NN];
__device__ int   g_sel[BB * KK];
__device__ unsigned char g_mask[BB * NN];
// split-bf16 operands for the tensor GEMM
__device__ __align__(16) __nv_bfloat16 g_Phi[(long)BB * KK * NN];  // [b][slot][j]
__device__ __align__(16) __nv_bfloat16 g_Plo[(long)BB * KK * NN];
__device__ __align__(16) __nv_bfloat16 g_hhi[(long)BB * NN * CC];  // [b][j][c] row-major
__device__ __align__(16) __nv_bfloat16 g_hlo[(long)BB * NN * CC];

__device__ __forceinline__ float lrelu(float v) { return v >= 0.f ? v : 0.01f * v; }

__device__ __forceinline__ ull dupf(float v) {
    ull r; asm("mov.b64 %0, {%1, %1};" : "=l"(r) : "f"(v)); return r;
}

// ---------------------------------------------------------------------------
// k_h (fused): h = x@W -> split bf16 row-major; s1 = h@a1, s2 = h@a2;
// x column partial sums; zero g_rank.  512 blocks x 128 thr, 32 rows/block.
// ---------------------------------------------------------------------------
__global__ void __launch_bounds__(128) k_h(const float* __restrict__ x,
                                           const float* __restrict__ W,
                                           const float* __restrict__ a) {
    __shared__ __align__(16) float xs[32][128];
    int t = threadIdx.x;
    int g = t >> 5, lane = t & 31;
    long row0 = (long)blockIdx.x * 32;

    const float4* xsrc = (const float4*)(x + row0 * CC);
    float4* xdst = (float4*)xs;
#pragma unroll
    for (int q = 0; q < 8; q++) xdst[t + 128 * q] = xsrc[t + 128 * q];
    __syncthreads();

    ull acc[8][2];
#pragma unroll
    for (int r = 0; r < 8; r++) { acc[r][0] = 0; acc[r][1] = 0; }
    const ulonglong2* Wp = (const ulonglong2*)(W);

#pragma unroll 4
    for (int k = 0; k < 128; k += 2) {
        ulonglong2 w0 = Wp[(k + 0) * 32 + lane];
        ulonglong2 w1 = Wp[(k + 1) * 32 + lane];
#pragma unroll
        for (int r = 0; r < 8; r++) {
            float xk0, xk1;
            ull xv = *(const ull*)&xs[g * 8 + r][k];
            asm("mov.b64 {%0, %1}, %2;" : "=f"(xk0), "=f"(xk1) : "l"(xv));
            ull d0 = dupf(xk0), d1 = dupf(xk1);
            asm("fma.rn.f32x2 %0, %1, %2, %0;" : "+l"(acc[r][0]) : "l"(d0), "l"(w0.x));
            asm("fma.rn.f32x2 %0, %1, %2, %0;" : "+l"(acc[r][1]) : "l"(d0), "l"(w0.y));
            asm("fma.rn.f32x2 %0, %1, %2, %0;" : "+l"(acc[r][0]) : "l"(d1), "l"(w1.x));
            asm("fma.rn.f32x2 %0, %1, %2, %0;" : "+l"(acc[r][1]) : "l"(d1), "l"(w1.y));
        }
    }

    float4 a1v = ((const float4*)a)[lane];
    float4 a2v = ((const float4*)(a + CC))[lane];

#pragma unroll
    for (int r = 0; r < 8; r++) {
        long row = row0 + g * 8 + r;
        float v0, v1, v2, v3;
        asm("mov.b64 {%0, %1}, %2;" : "=f"(v0), "=f"(v1) : "l"(acc[r][0]));
        asm("mov.b64 {%0, %1}, %2;" : "=f"(v2), "=f"(v3) : "l"(acc[r][1]));

        // split bf16 store (row-major)
        __nv_bfloat16 h0 = __float2bfloat16(v0), h1 = __float2bfloat16(v1);
        __nv_bfloat16 h2 = __float2bfloat16(v2), h3 = __float2bfloat16(v3);
        __nv_bfloat16 l0 = __float2bfloat16(v0 - __bfloat162float(h0));
        __nv_bfloat16 l1 = __float2bfloat16(v1 - __bfloat162float(h1));
        __nv_bfloat16 l2 = __float2bfloat16(v2 - __bfloat162float(h2));
        __nv_bfloat16 l3 = __float2bfloat16(v3 - __bfloat162float(h3));
        __nv_bfloat162 hp01; hp01.x = h0; hp01.y = h1;
        __nv_bfloat162 hp23; hp23.x = h2; hp23.y = h3;
        __nv_bfloat162 lp01; lp01.x = l0; lp01.y = l1;
        __nv_bfloat162 lp23; lp23.x = l2; lp23.y = l3;
        uint2 hv; hv.x = *(uint*)&hp01; hv.y = *(uint*)&hp23;
        uint2 lv; lv.x = *(uint*)&lp01; lv.y = *(uint*)&lp23;
        *(uint2*)&g_hhi[row * CC + 4 * lane] = hv;
        *(uint2*)&g_hlo[row * CC + 4 * lane] = lv;

        // s1/s2 via butterfly
        float p1 = v0 * a1v.x + v1 * a1v.y + v2 * a1v.z + v3 * a1v.w;
        float p2 = v0 * a2v.x + v1 * a2v.y + v2 * a2v.z + v3 * a2v.w;
#pragma unroll
        for (int o = 16; o; o >>= 1) {
            p1 += __shfl_xor_sync(0xffffffffu, p1, o);
            p2 += __shfl_xor_sync(0xffffffffu, p2, o);
        }
        if (lane == 0) { g_s1[row] = p1; g_s2[row] = p2; g_rank[row] = 0; }
    }

    // column partial sums of x tile (xs unchanged)
    float s = 0.f;
#pragma unroll 8
    for (int r = 0; r < 32; r++) s += xs[r][t];
    g_xpart[blockIdx.x * CC + t] = s;
}

// ---------------------------------------------------------------------------
// k_rank: exact top-512 membership by rank counting. 4 keys/thread.
// grid (2 i-chunks of 1024, 8 j-chunks of 256, B).
// ---------------------------------------------------------------------------
__device__ __forceinline__ ull rankkey(int b, int idx) {
    unsigned u = __float_as_uint(g_s1[b * NN + idx]);
    unsigned key = (u & 0x80000000u) ? ~u : (u | 0x80000000u);
    return ((ull)key << 11) | (unsigned)(NN - 1 - idx);
}

__global__ void __launch_bounds__(256) k_rank() {
    int b = blockIdx.z;
    int t = threadIdx.x;
    __shared__ ull jk[256];
    jk[t] = rankkey(b, blockIdx.y * 256 + t);
    __syncthreads();
    int i0 = blockIdx.x * 1024 + t;
    ull me0 = rankkey(b, i0);
    ull me1 = rankkey(b, i0 + 256);
    ull me2 = rankkey(b, i0 + 512);
    ull me3 = rankkey(b, i0 + 768);
    int c0 = 0, c1 = 0, c2 = 0, c3 = 0;
#pragma unroll 8
    for (int j = 0; j < 256; j++) {
        ull kj = jk[j];
        c0 += (kj > me0) ? 1 : 0;
        c1 += (kj > me1) ? 1 : 0;
        c2 += (kj > me2) ? 1 : 0;
        c3 += (kj > me3) ? 1 : 0;
    }
    atomicAdd(&g_rank[b * NN + i0], c0);
    atomicAdd(&g_rank[b * NN + i0 + 256], c1);
    atomicAdd(&g_rank[b * NN + i0 + 512], c2);
    atomicAdd(&g_rank[b * NN + i0 + 768], c3);
}

// ---------------------------------------------------------------------------
// k_prep: mask, max(s2), compaction, hp = relu((colmean x)@W)
// ---------------------------------------------------------------------------
__global__ void __launch_bounds__(256) k_prep(const float* __restrict__ W) {
    int b = blockIdx.x;
    int t = threadIdx.x;
    __shared__ float red[256];
    __shared__ int cnts[256];
    __shared__ int offs[256];
    __shared__ float xm[128];

    float m = -3.4e38f;
    for (int idx = t; idx < NN; idx += 256) m = fmaxf(m, g_s2[b * NN + idx]);
    red[t] = m;
    __syncthreads();
    for (int o = 128; o; o >>= 1) {
        if (t < o) red[t] = fmaxf(red[t], red[t + o]);
        __syncthreads();
    }
    if (t == 0) g_maxs2[b] = red[0];

    int base = t * 8;
    unsigned char f[8];
    int c = 0;
#pragma unroll
    for (int r = 0; r < 8; r++) {
        f[r] = (g_rank[b * NN + base + r] < KK) ? 1 : 0;
        g_mask[b * NN + base + r] = f[r];
        c += f[r];
    }
    cnts[t] = c;
    __syncthreads();
    if (t == 0) {
        int s = 0;
        for (int q = 0; q < 256; q++) { offs[q] = s; s += cnts[q]; }
    }
    __syncthreads();
    int pos = offs[t];
#pragma unroll
    for (int r = 0; r < 8; r++)
        if (f[r]) g_sel[b * KK + pos++] = base + r;

    if (t < 128) {
        float s = 0.f;
#pragma unroll 16
        for (int k = 0; k < 64; k++) s += g_xpart[(b * 64 + k) * CC + t];
        xm[t] = s * (1.0f / NN);
    }
    __syncthreads();
    if (t < 128) {
        float acc = 0.f;
#pragma unroll 8
        for (int k = 0; k < 128; k++) acc = fmaf(xm[k], W[k * CC + t], acc);
        g_hp[b * CC + t] = fmaxf(acc, 0.f);
    }
}

// ---------------------------------------------------------------------------
// k_P: materialize P (softmax numerators) as split bf16 + row sums Z.
// ---------------------------------------------------------------------------
__global__ void __launch_bounds__(256) k_P() {
    int b = blockIdx.y;
    int t = threadIdx.x, warp = t >> 5, lane = t & 31;
    int slot = blockIdx.x * 8 + warp;
    int i = g_sel[b * KK + slot];
    float s1 = g_s1[b * NN + i];
    float M = lrelu(s1 + g_maxs2[b]);
    const float* s2b = g_s2 + b * NN;
    uint* Phi = (uint*)g_Phi;
    uint* Plo = (uint*)g_Plo;
    long rowbase = ((long)b * KK + slot) * NN;

    float z = 0.f;
#pragma unroll 4
    for (int q = 0; q < 32; q++) {
        int j0 = 2 * lane + 64 * q;
        float w0 = __expf(lrelu(s1 + s2b[j0]) - M);
        float w1 = __expf(lrelu(s1 + s2b[j0 + 1]) - M);
        z += w0 + w1;
        __nv_bfloat16 h0 = __float2bfloat16(w0);
        __nv_bfloat16 h1 = __float2bfloat16(w1);
        __nv_bfloat16 l0 = __float2bfloat16(w0 - __bfloat162float(h0));
        __nv_bfloat16 l1 = __float2bfloat16(w1 - __bfloat162float(h1));
        __nv_bfloat162 hp; hp.x = h0; hp.y = h1;
        __nv_bfloat162 lp; lp.x = l0; lp.y = l1;
        Phi[(rowbase + j0) >> 1] = *(uint*)&hp;
        Plo[(rowbase + j0) >> 1] = *(uint*)&lp;
    }
#pragma unroll
    for (int o = 16; o; o >>= 1) z += __shfl_xor_sync(0xffffffffu, z, o);
    if (lane == 0) g_Z[b * KK + slot] = z;
}

// ---------------------------------------------------------------------------
// k_gemm: D = P @ h via mma.sync bf16 (3 split passes), fp32 accumulate.
// Block tile 64M x 64N, 8 warps (2m x 4n) of 32M x 16N. K chunks of 64,
// cp.async double buffer. Fragments via ldmatrix.x4 (A) / ldmatrix.x4.trans (B
// straight from row-major h tiles — no transpose kernel needed).
// ---------------------------------------------------------------------------
#define PITCH 72
#define ARR (64 * PITCH)
#define STG_ELEMS (4 * ARR)
#define GEMM_SMEM (2 * STG_ELEMS * 2)

__device__ __forceinline__ void mma_bf16(float* d, const uint* a, const uint* bfr) {
    asm("mma.sync.aligned.m16n8k16.row.col.f32.bf16.bf16.f32 "
        "{%0,%1,%2,%3}, {%4,%5,%6,%7}, {%8,%9}, {%0,%1,%2,%3};"
        : "+f"(d[0]), "+f"(d[1]), "+f"(d[2]), "+f"(d[3])
        : "r"(a[0]), "r"(a[1]), "r"(a[2]), "r"(a[3]), "r"(bfr[0]), "r"(bfr[1]));
}

__device__ __forceinline__ void ldsm4(uint* r, uint addr) {
    asm volatile("ldmatrix.sync.aligned.m8n8.x4.shared.b16 {%0,%1,%2,%3}, [%4];"
                 : "=r"(r[0]), "=r"(r[1]), "=r"(r[2]), "=r"(r[3]) : "r"(addr));
}
__device__ __forceinline__ void ldsm4t(uint* r, uint addr) {
    asm volatile("ldmatrix.sync.aligned.m8n8.x4.trans.shared.b16 {%0,%1,%2,%3}, [%4];"
                 : "=r"(r[0]), "=r"(r[1]), "=r"(r[2]), "=r"(r[3]) : "r"(addr));
}

__global__ void __launch_bounds__(256) k_gemm(float* __restrict__ out) {
    extern __shared__ __align__(16) __nv_bfloat16 S[];
    int t = threadIdx.x, warp = t >> 5, lane = t & 31;
    int wm = warp >> 2, wn = warp & 3;
    int mt = blockIdx.x & 7, nt = blockIdx.x >> 3, b = blockIdx.y;

    // sources: A row stride NN, B row stride CC
    const __nv_bfloat16* srcA[2] = {
        g_Phi + ((long)b * KK + mt * 64) * NN,
        g_Plo + ((long)b * KK + mt * 64) * NN
    };
    const __nv_bfloat16* srcB[2] = {
        g_hhi + (long)b * NN * CC + nt * 64,
        g_hlo + (long)b * NN * CC + nt * 64
    };

#define COPY(buf, chunk)                                                          \
    {                                                                             \
        _Pragma("unroll")                                                         \
        for (int arr = 0; arr < 2; arr++) {                                       \
            const __nv_bfloat16* sp = srcA[arr] + (chunk) * 64;                   \
            uint dbase = (uint)__cvta_generic_to_shared(                          \
                S + (buf) * STG_ELEMS + arr * ARR);                               \
            _Pragma("unroll")                                                     \
            for (int q = 0; q < 2; q++) {                                         \
                int idx = t + 256 * q;                                            \
                int row = idx >> 3, seg = idx & 7;                                \
                asm volatile("cp.async.cg.shared.global [%0], [%1], 16;"          \
                             :: "r"(dbase + (row * PITCH + seg * 8) * 2),         \
                                "l"(sp + (long)row * NN + seg * 8) : "memory");   \
            }                                                                     \
        }                                                                         \
        _Pragma("unroll")                                                         \
        for (int arr = 0; arr < 2; arr++) {                                       \
            const __nv_bfloat16* sp = srcB[arr] + (long)(chunk) * 64 * CC;        \
            uint dbase = (uint)__cvta_generic_to_shared(                          \
                S + (buf) * STG_ELEMS + (2 + arr) * ARR);                         \
            _Pragma("unroll")                                                     \
            for (int q = 0; q < 2; q++) {                                         \
                int idx = t + 256 * q;                                            \
                int row = idx >> 3, seg = idx & 7;                                \
                asm volatile("cp.async.cg.shared.global [%0], [%1], 16;"          \
                             :: "r"(dbase + (row * PITCH + seg * 8) * 2),         \
                                "l"(sp + (long)row * CC + seg * 8) : "memory");   \
            }                                                                     \
        }                                                                         \
        asm volatile("cp.async.commit_group;" ::: "memory");                      \
    }

    float acc[2][2][4];
#pragma unroll
    for (int fm = 0; fm < 2; fm++)
#pragma unroll
        for (int fn = 0; fn < 2; fn++)
#pragma unroll
            for (int q = 0; q < 4; q++) acc[fm][fn][q] = 0.f;

    COPY(0, 0)

    int lg = lane & 15, lh = lane >> 4;

    for (int c = 0; c < 32; c++) {
        if (c + 1 < 32) {
            COPY((c + 1) & 1, c + 1)
            asm volatile("cp.async.wait_group 1;" ::: "memory");
        } else {
            asm volatile("cp.async.wait_group 0;" ::: "memory");
        }
        __syncthreads();

        uint Sb = (uint)__cvta_generic_to_shared(S + (c & 1) * STG_ELEMS);
        uint sAhi = Sb, sAlo = Sb + ARR * 2, sBhi = Sb + 2 * ARR * 2, sBlo = Sb + 3 * ARR * 2;

#pragma unroll
        for (int ks = 0; ks < 4; ks++) {
            int k0 = ks * 16;
            uint ahi[2][4], alo[2][4], bhi[4], blo[4];
#pragma unroll
            for (int fm = 0; fm < 2; fm++) {
                uint ra = (uint)((wm * 32 + fm * 16 + lg) * PITCH + k0 + lh * 8) * 2;
                ldsm4(ahi[fm], sAhi + ra);
                ldsm4(alo[fm], sAlo + ra);
            }
            uint rb = (uint)((k0 + lg) * PITCH + wn * 16 + lh * 8) * 2;
            ldsm4t(bhi, sBhi + rb);
            ldsm4t(blo, sBlo + rb);

#pragma unroll
            for (int fm = 0; fm < 2; fm++)
#pragma unroll
                for (int fn = 0; fn < 2; fn++) {
                    mma_bf16(acc[fm][fn], ahi[fm], bhi + 2 * fn);
                    mma_bf16(acc[fm][fn], ahi[fm], blo + 2 * fn);
                    mma_bf16(acc[fm][fn], alo[fm], bhi + 2 * fn);
                }
        }
        __syncthreads();
    }
#undef COPY

    int g = lane >> 2, tig = lane & 3;
    float* ob = out + (long)b * CC * NN;
#pragma unroll
    for (int fm = 0; fm < 2; fm++) {
        int slot0 = mt * 64 + wm * 32 + fm * 16 + g;
        int i0 = g_sel[b * KK + slot0];
        int i1 = g_sel[b * KK + slot0 + 8];
        float z0 = 1.f / g_Z[b * KK + slot0];
        float z1 = 1.f / g_Z[b * KK + slot0 + 8];
#pragma unroll
        for (int fn = 0; fn < 2; fn++) {
            int c0 = nt * 64 + wn * 16 + fn * 8 + 2 * tig;
            ob[(long)(c0)     * NN + i0] = fmaxf(acc[fm][fn][0] * z0, 0.f);
            ob[(long)(c0 + 1) * NN + i0] = fmaxf(acc[fm][fn][1] * z0, 0.f);
            ob[(long)(c0)     * NN + i1] = fmaxf(acc[fm][fn][2] * z1, 0.f);
            ob[(long)(c0 + 1) * NN + i1] = fmaxf(acc[fm][fn][3] * z1, 0.f);
        }
    }
}

// ---------------------------------------------------------------------------
// k_fill: masked rows get the shared relu(colmean h) vector.
// ---------------------------------------------------------------------------
__global__ void __launch_bounds__(256) k_fill(float* __restrict__ out) {
    int idx = blockIdx.x * 256 + threadIdx.x;
    int i = idx & (NN - 1);
    int c = (idx >> 11) & (CC - 1);
    int b = idx >> 18;
    if (!g_mask[b * NN + i]) out[idx] = g_hp[b * CC + c];
}

// ---------------------------------------------------------------------------
extern "C" void kernel_launch(void* const* d_in, const int* in_sizes, int n_in,
                              void* d_out, int out_size) {
    const float* x = nullptr;
    const float* W = nullptr;
    const float* a = nullptr;
    for (int k = 0; k < n_in; k++) {
        if (in_sizes[k] == BB * NN * CC)      x = (const float*)d_in[k];
        else if (in_sizes[k] == CC * CC)      W = (const float*)d_in[k];
        else if (in_sizes[k] == 2 * CC)       a = (const float*)d_in[k];
    }
    float* out = (float*)d_out;

    static int smem_set = 0;
    if (!smem_set) {
        cudaFuncSetAttribute(k_gemm, cudaFuncAttributeMaxDynamicSharedMemorySize, GEMM_SMEM);
        smem_set = 1;
    }

    k_h    <<<BB * NN / 32, 128>>>(x, W, a);
    k_rank <<<dim3(2, 8, BB), 256>>>();
    k_prep <<<BB, 256>>>(W);
    k_P    <<<dim3(64, BB), 256>>>();
    k_gemm <<<dim3(16, BB), 256, GEMM_SMEM>>>(out);
    k_fill <<<BB * CC * NN / 256, 256>>>(out);
}

// round 8
// speedup vs baseline: 1.8476x; 1.0365x over previous
#include <cuda_runtime.h>
#include <cuda_bf16.h>

#define BB 8
#define NN 2048
#define CC 128
#define KK 512

typedef unsigned long long ull;
typedef unsigned int uint;

// ---------------- device scratch (no allocations allowed) ----------------
__device__ float g_s1[BB * NN];
__device__ float g_s2[BB * NN];
__device__ float g_maxs2[BB];
__device__ float g_hp[BB * CC];
__device__ float g_xpart[512 * CC];
__device__ float g_Z2[BB * KK * 2];         // per-half-row softmax partial sums
__device__ int   g_rank[BB * NN];
__device__ int   g_sel[BB * KK];
__device__ unsigned char g_mask[BB * NN];
__device__ __align__(16) ull g_Wp[64 * CC]; // (W[2k][c], W[2k+1][c]) pairs
// split-bf16 operands for the tensor GEMM
__device__ __align__(16) __nv_bfloat16 g_Phi[(long)BB * KK * NN];  // [b][slot][j]
__device__ __align__(16) __nv_bfloat16 g_Plo[(long)BB * KK * NN];
__device__ __align__(16) __nv_bfloat16 g_hhi[(long)BB * NN * CC];  // [b][j][c]
__device__ __align__(16) __nv_bfloat16 g_hlo[(long)BB * NN * CC];

__device__ __forceinline__ float lrelu(float v) { return v >= 0.f ? v : 0.01f * v; }

// packed bf16x2 convert: result = {lo=a, hi=b}
__device__ __forceinline__ uint cvt2(float a, float b) {
    uint r;
    asm("cvt.rn.bf16x2.f32 %0, %1, %2;" : "=r"(r) : "f"(b), "f"(a));
    return r;
}

// ---------------------------------------------------------------------------
// k_wp: pre-pair W rows across consecutive k. 32 blocks x 256 thr.
// ---------------------------------------------------------------------------
__global__ void __launch_bounds__(256) k_wp(const float* __restrict__ W) {
    int idx = blockIdx.x * 256 + threadIdx.x;     // 8192 entries
    int k2 = idx >> 7, c = idx & 127;
    float w0 = W[(2 * k2) * CC + c];
    float w1 = W[(2 * k2 + 1) * CC + c];
    ull p;
    asm("mov.b64 %0, {%1, %2};" : "=l"(p) : "f"(w0), "f"(w1));
    g_Wp[idx] = p;
}

// ---------------------------------------------------------------------------
// k_h (fused): h = x@W -> split bf16 row-major; s1/s2; x col partials; rank=0.
// k-paired FFMA2: no dup MOVs. 512 blocks x 128 thr, 32 rows/block.
// ---------------------------------------------------------------------------
__global__ void __launch_bounds__(128) k_h(const float* __restrict__ x,
                                           const float* __restrict__ a) {
    __shared__ __align__(16) float xs[32][128];
    int t = threadIdx.x;
    int g = t >> 5, lane = t & 31;
    long row0 = (long)blockIdx.x * 32;

    const float4* xsrc = (const float4*)(x + row0 * CC);
    float4* xdst = (float4*)xs;
#pragma unroll
    for (int q = 0; q < 8; q++) xdst[t + 128 * q] = xsrc[t + 128 * q];
    __syncthreads();

    ull acc[8][4];   // [row][col]; pair lanes hold the two k-phases
#pragma unroll
    for (int r = 0; r < 8; r++)
#pragma unroll
        for (int c = 0; c < 4; c++) acc[r][c] = 0;

    const ulonglong2* Wp2 = (const ulonglong2*)g_Wp;   // 64 ulonglong2 per k2 row

#pragma unroll 4
    for (int k2 = 0; k2 < 64; k2++) {
        ulonglong2 wa = Wp2[k2 * 64 + 2 * lane];       // cols 4l, 4l+1
        ulonglong2 wb = Wp2[k2 * 64 + 2 * lane + 1];   // cols 4l+2, 4l+3
#pragma unroll
        for (int r = 0; r < 8; r++) {
            ull xv = *(const ull*)&xs[g * 8 + r][2 * k2];
            asm("fma.rn.f32x2 %0, %1, %2, %0;" : "+l"(acc[r][0]) : "l"(xv), "l"(wa.x));
            asm("fma.rn.f32x2 %0, %1, %2, %0;" : "+l"(acc[r][1]) : "l"(xv), "l"(wa.y));
            asm("fma.rn.f32x2 %0, %1, %2, %0;" : "+l"(acc[r][2]) : "l"(xv), "l"(wb.x));
            asm("fma.rn.f32x2 %0, %1, %2, %0;" : "+l"(acc[r][3]) : "l"(xv), "l"(wb.y));
        }
    }

    float4 a1v = ((const float4*)a)[lane];
    float4 a2v = ((const float4*)(a + CC))[lane];

#pragma unroll
    for (int r = 0; r < 8; r++) {
        long row = row0 + g * 8 + r;
        float v[4];
#pragma unroll
        for (int c = 0; c < 4; c++) {
            float lo, hi;
            asm("mov.b64 {%0, %1}, %2;" : "=f"(lo), "=f"(hi) : "l"(acc[r][c]));
            v[c] = lo + hi;
        }

        uint hp01 = cvt2(v[0], v[1]);
        uint hp23 = cvt2(v[2], v[3]);
        float f0 = __uint_as_float(hp01 << 16), f1 = __uint_as_float(hp01 & 0xffff0000u);
        float f2 = __uint_as_float(hp23 << 16), f3 = __uint_as_float(hp23 & 0xffff0000u);
        uint lp01 = cvt2(v[0] - f0, v[1] - f1);
        uint lp23 = cvt2(v[2] - f2, v[3] - f3);
        uint2 hv; hv.x = hp01; hv.y = hp23;
        uint2 lv; lv.x = lp01; lv.y = lp23;
        *(uint2*)&g_hhi[row * CC + 4 * lane] = hv;
        *(uint2*)&g_hlo[row * CC + 4 * lane] = lv;

        float p1 = v[0] * a1v.x + v[1] * a1v.y + v[2] * a1v.z + v[3] * a1v.w;
        float p2 = v[0] * a2v.x + v[1] * a2v.y + v[2] * a2v.z + v[3] * a2v.w;
#pragma unroll
        for (int o = 16; o; o >>= 1) {
            p1 += __shfl_xor_sync(0xffffffffu, p1, o);
            p2 += __shfl_xor_sync(0xffffffffu, p2, o);
        }
        if (lane == 0) { g_s1[row] = p1; g_s2[row] = p2; g_rank[row] = 0; }
    }

    float s = 0.f;
#pragma unroll 8
    for (int r = 0; r < 32; r++) s += xs[r][t];
    g_xpart[blockIdx.x * CC + t] = s;
}

// ---------------------------------------------------------------------------
// k_rank: exact top-512 membership by rank counting. 4 keys/thread.
// ---------------------------------------------------------------------------
__device__ __forceinline__ ull rankkey(int b, int idx) {
    unsigned u = __float_as_uint(g_s1[b * NN + idx]);
    unsigned key = (u & 0x80000000u) ? ~u : (u | 0x80000000u);
    return ((ull)key << 11) | (unsigned)(NN - 1 - idx);
}

__global__ void __launch_bounds__(256) k_rank() {
    int b = blockIdx.z;
    int t = threadIdx.x;
    __shared__ ull jk[256];
    jk[t] = rankkey(b, blockIdx.y * 256 + t);
    __syncthreads();
    int i0 = blockIdx.x * 1024 + t;
    ull me0 = rankkey(b, i0);
    ull me1 = rankkey(b, i0 + 256);
    ull me2 = rankkey(b, i0 + 512);
    ull me3 = rankkey(b, i0 + 768);
    int c0 = 0, c1 = 0, c2 = 0, c3 = 0;
#pragma unroll 8
    for (int j = 0; j < 256; j++) {
        ull kj = jk[j];
        c0 += (kj > me0) ? 1 : 0;
        c1 += (kj > me1) ? 1 : 0;
        c2 += (kj > me2) ? 1 : 0;
        c3 += (kj > me3) ? 1 : 0;
    }
    atomicAdd(&g_rank[b * NN + i0], c0);
    atomicAdd(&g_rank[b * NN + i0 + 256], c1);
    atomicAdd(&g_rank[b * NN + i0 + 512], c2);
    atomicAdd(&g_rank[b * NN + i0 + 768], c3);
}

// ---------------------------------------------------------------------------
// k_prep: mask, max(s2), compaction, hp = relu((colmean x)@W)
// ---------------------------------------------------------------------------
__global__ void __launch_bounds__(256) k_prep(const float* __restrict__ W) {
    int b = blockIdx.x;
    int t = threadIdx.x;
    __shared__ float red[256];
    __shared__ int cnts[256];
    __shared__ int offs[256];
    __shared__ float xm[128];

    float m = -3.4e38f;
    for (int idx = t; idx < NN; idx += 256) m = fmaxf(m, g_s2[b * NN + idx]);
    red[t] = m;
    __syncthreads();
    for (int o = 128; o; o >>= 1) {
        if (t < o) red[t] = fmaxf(red[t], red[t + o]);
        __syncthreads();
    }
    if (t == 0) g_maxs2[b] = red[0];

    int base = t * 8;
    unsigned char f[8];
    int c = 0;
#pragma unroll
    for (int r = 0; r < 8; r++) {
        f[r] = (g_rank[b * NN + base + r] < KK) ? 1 : 0;
        g_mask[b * NN + base + r] = f[r];
        c += f[r];
    }
    cnts[t] = c;
    __syncthreads();
    if (t == 0) {
        int s = 0;
        for (int q = 0; q < 256; q++) { offs[q] = s; s += cnts[q]; }
    }
    __syncthreads();
    int pos = offs[t];
#pragma unroll
    for (int r = 0; r < 8; r++)
        if (f[r]) g_sel[b * KK + pos++] = base + r;

    if (t < 128) {
        float s = 0.f;
#pragma unroll 16
        for (int k = 0; k < 64; k++) s += g_xpart[(b * 64 + k) * CC + t];
        xm[t] = s * (1.0f / NN);
    }
    __syncthreads();
    if (t < 128) {
        float acc = 0.f;
#pragma unroll 8
        for (int k = 0; k < 128; k++) acc = fmaf(xm[k], W[k * CC + t], acc);
        g_hp[b * CC + t] = fmaxf(acc, 0.f);
    }
}

// ---------------------------------------------------------------------------
// k_P: P (softmax numerators) as split bf16 + per-half row sums.
// 2 warps per row, 4 rows per block; grid (128, B) = 1024 blocks.
// ---------------------------------------------------------------------------
__global__ void __launch_bounds__(256) k_P() {
    int b = blockIdx.y;
    int t = threadIdx.x, warp = t >> 5, lane = t & 31;
    int rloc = warp >> 1, half = warp & 1;
    int slot = blockIdx.x * 4 + rloc;
    int i = g_sel[b * KK + slot];
    float s1 = g_s1[b * NN + i];
    float M = lrelu(s1 + g_maxs2[b]);
    const float* s2b = g_s2 + b * NN + half * 1024;
    uint* Phi = (uint*)g_Phi;
    uint* Plo = (uint*)g_Plo;
    long rowbase = ((long)b * KK + slot) * NN + half * 1024;

    float z = 0.f;
#pragma unroll 4
    for (int q = 0; q < 16; q++) {
        int j0 = 2 * lane + 64 * q;
        float2 s2v = *(const float2*)(s2b + j0);
        float w0 = __expf(lrelu(s1 + s2v.x) - M);
        float w1 = __expf(lrelu(s1 + s2v.y) - M);
        z += w0 + w1;
        uint hp = cvt2(w0, w1);
        float f0 = __uint_as_float(hp << 16);
        float f1 = __uint_as_float(hp & 0xffff0000u);
        uint lp = cvt2(w0 - f0, w1 - f1);
        Phi[(rowbase + j0) >> 1] = hp;
        Plo[(rowbase + j0) >> 1] = lp;
    }
#pragma unroll
    for (int o = 16; o; o >>= 1) z += __shfl_xor_sync(0xffffffffu, z, o);
    if (lane == 0) g_Z2[(b * KK + slot) * 2 + half] = z;
}

// ---------------------------------------------------------------------------
// k_gemm: D = P @ h via mma.sync bf16 (3 split passes) + fused fill of
// unmasked output rows. Block tile 64M x 64N, ldmatrix fragments,
// cp.async double buffer.
// ---------------------------------------------------------------------------
#define PITCH 72
#define ARR (64 * PITCH)
#define STG_ELEMS (4 * ARR)
#define GEMM_SMEM (2 * STG_ELEMS * 2)

__device__ __forceinline__ void mma_bf16(float* d, const uint* a, const uint* bfr) {
    asm("mma.sync.aligned.m16n8k16.row.col.f32.bf16.bf16.f32 "
        "{%0,%1,%2,%3}, {%4,%5,%6,%7}, {%8,%9}, {%0,%1,%2,%3};"
        : "+f"(d[0]), "+f"(d[1]), "+f"(d[2]), "+f"(d[3])
        : "r"(a[0]), "r"(a[1]), "r"(a[2]), "r"(a[3]), "r"(bfr[0]), "r"(bfr[1]));
}

__device__ __forceinline__ void ldsm4(uint* r, uint addr) {
    asm volatile("ldmatrix.sync.aligned.m8n8.x4.shared.b16 {%0,%1,%2,%3}, [%4];"
                 : "=r"(r[0]), "=r"(r[1]), "=r"(r[2]), "=r"(r[3]) : "r"(addr));
}
__device__ __forceinline__ void ldsm4t(uint* r, uint addr) {
    asm volatile("ldmatrix.sync.aligned.m8n8.x4.trans.shared.b16 {%0,%1,%2,%3}, [%4];"
                 : "=r"(r[0]), "=r"(r[1]), "=r"(r[2]), "=r"(r[3]) : "r"(addr));
}

__global__ void __launch_bounds__(256) k_gemm(float* __restrict__ out) {
    extern __shared__ __align__(16) __nv_bfloat16 S[];
    int t = threadIdx.x, warp = t >> 5, lane = t & 31;
    int wm = warp >> 2, wn = warp & 3;
    int mt = blockIdx.x & 7, nt = blockIdx.x >> 3, b = blockIdx.y;

    const __nv_bfloat16* srcA[2] = {
        g_Phi + ((long)b * KK + mt * 64) * NN,
        g_Plo + ((long)b * KK + mt * 64) * NN
    };
    const __nv_bfloat16* srcB[2] = {
        g_hhi + (long)b * NN * CC + nt * 64,
        g_hlo + (long)b * NN * CC + nt * 64
    };

#define COPY(buf, chunk)                                                          \
    {                                                                             \
        _Pragma("unroll")                                                         \
        for (int arr = 0; arr < 2; arr++) {                                       \
            const __nv_bfloat16* sp = srcA[arr] + (chunk) * 64;                   \
            uint dbase = (uint)__cvta_generic_to_shared(                          \
                S + (buf) * STG_ELEMS + arr * ARR);                               \
            _Pragma("unroll")                                                     \
            for (int q = 0; q < 2; q++) {                                         \
                int idx = t + 256 * q;                                            \
                int row = idx >> 3, seg = idx & 7;                                \
                asm volatile("cp.async.cg.shared.global [%0], [%1], 16;"          \
                             :: "r"(dbase + (row * PITCH + seg * 8) * 2),         \
                                "l"(sp + (long)row * NN + seg * 8) : "memory");   \
            }                                                                     \
        }                                                                         \
        _Pragma("unroll")                                                         \
        for (int arr = 0; arr < 2; arr++) {                                       \
            const __nv_bfloat16* sp = srcB[arr] + (long)(chunk) * 64 * CC;        \
            uint dbase = (uint)__cvta_generic_to_shared(                          \
                S + (buf) * STG_ELEMS + (2 + arr) * ARR);                         \
            _Pragma("unroll")                                                     \
            for (int q = 0; q < 2; q++) {                                         \
                int idx = t + 256 * q;                                            \
                int row = idx >> 3, seg = idx & 7;                                \
                asm volatile("cp.async.cg.shared.global [%0], [%1], 16;"          \
                             :: "r"(dbase + (row * PITCH + seg * 8) * 2),         \
                                "l"(sp + (long)row * CC + seg * 8) : "memory");   \
            }                                                                     \
        }                                                                         \
        asm volatile("cp.async.commit_group;" ::: "memory");                      \
    }

    float acc[2][2][4];
#pragma unroll
    for (int fm = 0; fm < 2; fm++)
#pragma unroll
        for (int fn = 0; fn < 2; fn++)
#pragma unroll
            for (int q = 0; q < 4; q++) acc[fm][fn][q] = 0.f;

    COPY(0, 0)

    // ---- fused fill: unmasked rows i in [mt*256, +256), cols [nt*64, +64) ----
    {
        int i = mt * 256 + t;
        if (!g_mask[b * NN + i]) {
            float* ob = out + (long)b * CC * NN + i;
            const float* hpb = g_hp + b * CC + nt * 64;
#pragma unroll 8
            for (int c = 0; c < 64; c++)
                ob[(long)(nt * 64 + c) * NN] = hpb[c];
        }
    }

    int lg = lane & 15, lh = lane >> 4;

    for (int c = 0; c < 32; c++) {
        if (c + 1 < 32) {
            COPY((c + 1) & 1, c + 1)
            asm volatile("cp.async.wait_group 1;" ::: "memory");
        } else {
            asm volatile("cp.async.wait_group 0;" ::: "memory");
        }
        __syncthreads();

        uint Sb = (uint)__cvta_generic_to_shared(S + (c & 1) * STG_ELEMS);
        uint sAhi = Sb, sAlo = Sb + ARR * 2, sBhi = Sb + 2 * ARR * 2, sBlo = Sb + 3 * ARR * 2;

#pragma unroll
        for (int ks = 0; ks < 4; ks++) {
            int k0 = ks * 16;
            uint ahi[2][4], alo[2][4], bhi[4], blo[4];
#pragma unroll
            for (int fm = 0; fm < 2; fm++) {
                uint ra = (uint)((wm * 32 + fm * 16 + lg) * PITCH + k0 + lh * 8) * 2;
                ldsm4(ahi[fm], sAhi + ra);
                ldsm4(alo[fm], sAlo + ra);
            }
            uint rb = (uint)((k0 + lg) * PITCH + wn * 16 + lh * 8) * 2;
            ldsm4t(bhi, sBhi + rb);
            ldsm4t(blo, sBlo + rb);

#pragma unroll
            for (int fm = 0; fm < 2; fm++)
#pragma unroll
                for (int fn = 0; fn < 2; fn++) {
                    mma_bf16(acc[fm][fn], ahi[fm], bhi + 2 * fn);
                    mma_bf16(acc[fm][fn], ahi[fm], blo + 2 * fn);
                    mma_bf16(acc[fm][fn], alo[fm], bhi + 2 * fn);
                }
        }
        __syncthreads();
    }
#undef COPY

    int g = lane >> 2, tig = lane & 3;
    float* ob = out + (long)b * CC * NN;
#pragma unroll
    for (int fm = 0; fm < 2; fm++) {
        int slot0 = mt * 64 + wm * 32 + fm * 16 + g;
        int i0 = g_sel[b * KK + slot0];
        int i1 = g_sel[b * KK + slot0 + 8];
        float2 za = ((const float2*)g_Z2)[b * KK + slot0];
        float2 zb = ((const float2*)g_Z2)[b * KK + slot0 + 8];
        float z0 = 1.f / (za.x + za.y);
        float z1 = 1.f / (zb.x + zb.y);
#pragma unroll
        for (int fn = 0; fn < 2; fn++) {
            int c0 = nt * 64 + wn * 16 + fn * 8 + 2 * tig;
            ob[(long)(c0)     * NN + i0] = fmaxf(acc[fm][fn][0] * z0, 0.f);
            ob[(long)(c0 + 1) * NN + i0] = fmaxf(acc[fm][fn][1] * z0, 0.f);
            ob[(long)(c0)     * NN + i1] = fmaxf(acc[fm][fn][2] * z1, 0.f);
            ob[(long)(c0 + 1) * NN + i1] = fmaxf(acc[fm][fn][3] * z1, 0.f);
        }
    }
}

// ---------------------------------------------------------------------------
extern "C" void kernel_launch(void* const* d_in, const int* in_sizes, int n_in,
                              void* d_out, int out_size) {
    const float* x = nullptr;
    const float* W = nullptr;
    const float* a = nullptr;
    for (int k = 0; k < n_in; k++) {
        if (in_sizes[k] == BB * NN * CC)      x = (const float*)d_in[k];
        else if (in_sizes[k] == CC * CC)      W = (const float*)d_in[k];
        else if (in_sizes[k] == 2 * CC)       a = (const float*)d_in[k];
    }
    float* out = (float*)d_out;

    static int smem_set = 0;
    if (!smem_set) {
        cudaFuncSetAttribute(k_gemm, cudaFuncAttributeMaxDynamicSharedMemorySize, GEMM_SMEM);
        smem_set = 1;
    }

    k_wp   <<<32, 256>>>(W);
    k_h    <<<BB * NN / 32, 128>>>(x, a);
    k_rank <<<dim3(2, 8, BB), 256>>>();
    k_prep <<<BB, 256>>>(W);
    k_P    <<<dim3(128, BB), 256>>>();
    k_gemm <<<dim3(16, BB), 256, GEMM_SMEM>>>(out);
}

// round 9
// speedup vs baseline: 2.0395x; 1.1039x over previous
#include <cuda_runtime.h>
#include <cuda_bf16.h>

#define BB 8
#define NN 2048
#define CC 128
#define KK 512

typedef unsigned long long ull;
typedef unsigned int uint;

// ---------------- device scratch (no allocations allowed) ----------------
__device__ float g_s1[BB * NN];
__device__ float g_s2[BB * NN];
__device__ uint  g_maxs2i[BB];              // int-encoded max of s2 per batch
__device__ float g_hp[BB * CC];
__device__ float g_xpart[512 * CC];
__device__ float g_Z2[BB * KK * 2];         // per-half-row softmax partial sums
__device__ int   g_rank[BB * NN];
__device__ int   g_sel[BB * KK];            // slot = rank (any bijection works)
__device__ __align__(16) ull g_Wp[64 * CC]; // (W[2k][c], W[2k+1][c]) pairs
// split-bf16 operands for the tensor GEMM
__device__ __align__(16) __nv_bfloat16 g_Phi[(long)BB * KK * NN];  // [b][slot][j]
__device__ __align__(16) __nv_bfloat16 g_Plo[(long)BB * KK * NN];
__device__ __align__(16) __nv_bfloat16 g_hhi[(long)BB * NN * CC];  // [b][j][c]
__device__ __align__(16) __nv_bfloat16 g_hlo[(long)BB * NN * CC];

__device__ __forceinline__ float lrelu(float v) { return v >= 0.f ? v : 0.01f * v; }

__device__ __forceinline__ uint fkey(float f) {
    uint u = __float_as_uint(f);
    return (u & 0x80000000u) ? ~u : (u | 0x80000000u);
}
__device__ __forceinline__ float fdec(uint k) {
    uint u = (k & 0x80000000u) ? (k & 0x7FFFFFFFu) : ~k;
    return __uint_as_float(u);
}

// packed bf16x2 convert: result = {lo=a, hi=b}
__device__ __forceinline__ uint cvt2(float a, float b) {
    uint r;
    asm("cvt.rn.bf16x2.f32 %0, %1, %2;" : "=r"(r) : "f"(b), "f"(a));
    return r;
}

// ---------------------------------------------------------------------------
// k_wp: pre-pair W rows; block 0 also zero-inits g_maxs2i.
// ---------------------------------------------------------------------------
__global__ void __launch_bounds__(256) k_wp(const float* __restrict__ W) {
    int idx = blockIdx.x * 256 + threadIdx.x;
    if (blockIdx.x == 0 && threadIdx.x < BB) g_maxs2i[threadIdx.x] = 0u;
    int k2 = idx >> 7, c = idx & 127;
    float w0 = W[(2 * k2) * CC + c];
    float w1 = W[(2 * k2 + 1) * CC + c];
    ull p;
    asm("mov.b64 %0, {%1, %2};" : "=l"(p) : "f"(w0), "f"(w1));
    g_Wp[idx] = p;
}

// ---------------------------------------------------------------------------
// k_h (fused): h = x@W -> split bf16; s1/s2; s2 block-max -> atomicMax;
// x col partials; rank=0.  512 blocks x 128 thr, 32 rows/block.
// ---------------------------------------------------------------------------
__global__ void __launch_bounds__(128) k_h(const float* __restrict__ x,
                                           const float* __restrict__ a) {
    __shared__ __align__(16) float xs[32][128];
    __shared__ uint wmax[4];
    int t = threadIdx.x;
    int g = t >> 5, lane = t & 31;
    long row0 = (long)blockIdx.x * 32;
    int b = blockIdx.x >> 6;     // 64 blocks per batch

    const float4* xsrc = (const float4*)(x + row0 * CC);
    float4* xdst = (float4*)xs;
#pragma unroll
    for (int q = 0; q < 8; q++) xdst[t + 128 * q] = xsrc[t + 128 * q];
    __syncthreads();

    ull acc[8][4];
#pragma unroll
    for (int r = 0; r < 8; r++)
#pragma unroll
        for (int c = 0; c < 4; c++) acc[r][c] = 0;

    const ulonglong2* Wp2 = (const ulonglong2*)g_Wp;

#pragma unroll 4
    for (int k2 = 0; k2 < 64; k2++) {
        ulonglong2 wa = Wp2[k2 * 64 + 2 * lane];
        ulonglong2 wb = Wp2[k2 * 64 + 2 * lane + 1];
#pragma unroll
        for (int r = 0; r < 8; r++) {
            ull xv = *(const ull*)&xs[g * 8 + r][2 * k2];
            asm("fma.rn.f32x2 %0, %1, %2, %0;" : "+l"(acc[r][0]) : "l"(xv), "l"(wa.x));
            asm("fma.rn.f32x2 %0, %1, %2, %0;" : "+l"(acc[r][1]) : "l"(xv), "l"(wa.y));
            asm("fma.rn.f32x2 %0, %1, %2, %0;" : "+l"(acc[r][2]) : "l"(xv), "l"(wb.x));
            asm("fma.rn.f32x2 %0, %1, %2, %0;" : "+l"(acc[r][3]) : "l"(xv), "l"(wb.y));
        }
    }

    float4 a1v = ((const float4*)a)[lane];
    float4 a2v = ((const float4*)(a + CC))[lane];
    float s2max = -3.4e38f;

#pragma unroll
    for (int r = 0; r < 8; r++) {
        long row = row0 + g * 8 + r;
        float v[4];
#pragma unroll
        for (int c = 0; c < 4; c++) {
            float lo, hi;
            asm("mov.b64 {%0, %1}, %2;" : "=f"(lo), "=f"(hi) : "l"(acc[r][c]));
            v[c] = lo + hi;
        }

        uint hp01 = cvt2(v[0], v[1]);
        uint hp23 = cvt2(v[2], v[3]);
        float f0 = __uint_as_float(hp01 << 16), f1 = __uint_as_float(hp01 & 0xffff0000u);
        float f2 = __uint_as_float(hp23 << 16), f3 = __uint_as_float(hp23 & 0xffff0000u);
        uint lp01 = cvt2(v[0] - f0, v[1] - f1);
        uint lp23 = cvt2(v[2] - f2, v[3] - f3);
        uint2 hv; hv.x = hp01; hv.y = hp23;
        uint2 lv; lv.x = lp01; lv.y = lp23;
        *(uint2*)&g_hhi[row * CC + 4 * lane] = hv;
        *(uint2*)&g_hlo[row * CC + 4 * lane] = lv;

        float p1 = v[0] * a1v.x + v[1] * a1v.y + v[2] * a1v.z + v[3] * a1v.w;
        float p2 = v[0] * a2v.x + v[1] * a2v.y + v[2] * a2v.z + v[3] * a2v.w;
#pragma unroll
        for (int o = 16; o; o >>= 1) {
            p1 += __shfl_xor_sync(0xffffffffu, p1, o);
            p2 += __shfl_xor_sync(0xffffffffu, p2, o);
        }
        s2max = fmaxf(s2max, p2);
        if (lane == 0) { g_s1[row] = p1; g_s2[row] = p2; g_rank[row] = 0; }
    }

    if (lane == 0) wmax[g] = fkey(s2max);

    float s = 0.f;
#pragma unroll 8
    for (int r = 0; r < 32; r++) s += xs[r][t];
    g_xpart[blockIdx.x * CC + t] = s;

    __syncthreads();
    if (t == 0) {
        uint m = max(max(wmax[0], wmax[1]), max(wmax[2], wmax[3]));
        atomicMax(&g_maxs2i[b], m);
    }
}

// ---------------------------------------------------------------------------
// k_rank: exact top-512 membership by rank counting. 4 keys/thread.
// ---------------------------------------------------------------------------
__device__ __forceinline__ ull rankkey(int b, int idx) {
    return ((ull)fkey(g_s1[b * NN + idx]) << 11) | (unsigned)(NN - 1 - idx);
}

__global__ void __launch_bounds__(256) k_rank() {
    int b = blockIdx.z;
    int t = threadIdx.x;
    __shared__ ull jk[256];
    jk[t] = rankkey(b, blockIdx.y * 256 + t);
    __syncthreads();
    int i0 = blockIdx.x * 1024 + t;
    ull me0 = rankkey(b, i0);
    ull me1 = rankkey(b, i0 + 256);
    ull me2 = rankkey(b, i0 + 512);
    ull me3 = rankkey(b, i0 + 768);
    int c0 = 0, c1 = 0, c2 = 0, c3 = 0;
#pragma unroll 8
    for (int j = 0; j < 256; j++) {
        ull kj = jk[j];
        c0 += (kj > me0) ? 1 : 0;
        c1 += (kj > me1) ? 1 : 0;
        c2 += (kj > me2) ? 1 : 0;
        c3 += (kj > me3) ? 1 : 0;
    }
    atomicAdd(&g_rank[b * NN + i0], c0);
    atomicAdd(&g_rank[b * NN + i0 + 256], c1);
    atomicAdd(&g_rank[b * NN + i0 + 512], c2);
    atomicAdd(&g_rank[b * NN + i0 + 768], c3);
}

// ---------------------------------------------------------------------------
// k_sel: grid (2, B).
//  block x=0: scatter g_sel[rank] = i  (ranks 0..511 are a permutation)
//  block x=1: hp = relu((colmean x) @ W)  (2 threads per col, k-split)
// ---------------------------------------------------------------------------
__global__ void __launch_bounds__(256) k_sel(const float* __restrict__ W) {
    int b = blockIdx.y;
    int t = threadIdx.x;
    if (blockIdx.x == 0) {
#pragma unroll
        for (int r = 0; r < 8; r++) {
            int i = t * 8 + r;
            int rk = g_rank[b * NN + i];
            if (rk < KK) g_sel[b * KK + rk] = i;
        }
    } else {
        __shared__ float xm[128];
        __shared__ float part[256];
        // colmean: thread t<128 col t sums rows [0,32), t>=128 col t-128 rows [32,64)
        int c = t & 127, half = t >> 7;
        float s = 0.f;
#pragma unroll 8
        for (int k = half * 32; k < half * 32 + 32; k++)
            s += g_xpart[(b * 64 + k) * CC + c];
        part[t] = s;
        __syncthreads();
        if (half == 0) xm[c] = (part[c] + part[c + 128]) * (1.0f / NN);
        __syncthreads();
        // dot: 2 threads per col, k halves
        float acc = 0.f;
#pragma unroll 8
        for (int k = half * 64; k < half * 64 + 64; k++)
            acc = fmaf(xm[k], W[k * CC + c], acc);
        part[t] = acc;
        __syncthreads();
        if (half == 0) g_hp[b * CC + c] = fmaxf(part[c] + part[c + 128], 0.f);
    }
}

// ---------------------------------------------------------------------------
// k_P: P (softmax numerators) as split bf16 + per-half row sums.
// 2 warps per row, 4 rows per block; grid (128, B) = 1024 blocks.
// ---------------------------------------------------------------------------
__global__ void __launch_bounds__(256) k_P() {
    int b = blockIdx.y;
    int t = threadIdx.x, warp = t >> 5, lane = t & 31;
    int rloc = warp >> 1, half = warp & 1;
    int slot = blockIdx.x * 4 + rloc;
    int i = g_sel[b * KK + slot];
    float s1 = g_s1[b * NN + i];
    float M = lrelu(s1 + fdec(g_maxs2i[b]));
    const float* s2b = g_s2 + b * NN + half * 1024;
    uint* Phi = (uint*)g_Phi;
    uint* Plo = (uint*)g_Plo;
    long rowbase = ((long)b * KK + slot) * NN + half * 1024;

    float z = 0.f;
#pragma unroll 4
    for (int q = 0; q < 16; q++) {
        int j0 = 2 * lane + 64 * q;
        float2 s2v = *(const float2*)(s2b + j0);
        float w0 = __expf(lrelu(s1 + s2v.x) - M);
        float w1 = __expf(lrelu(s1 + s2v.y) - M);
        z += w0 + w1;
        uint hp = cvt2(w0, w1);
        float f0 = __uint_as_float(hp << 16);
        float f1 = __uint_as_float(hp & 0xffff0000u);
        uint lp = cvt2(w0 - f0, w1 - f1);
        Phi[(rowbase + j0) >> 1] = hp;
        Plo[(rowbase + j0) >> 1] = lp;
    }
#pragma unroll
    for (int o = 16; o; o >>= 1) z += __shfl_xor_sync(0xffffffffu, z, o);
    if (lane == 0) g_Z2[(b * KK + slot) * 2 + half] = z;
}

// ---------------------------------------------------------------------------
// k_gemm: D = P @ h via mma.sync bf16 (3 split passes) + fused fill of
// unselected output rows (g_rank >= KK).
// ---------------------------------------------------------------------------
#define PITCH 72
#define ARR (64 * PITCH)
#define STG_ELEMS (4 * ARR)
#define GEMM_SMEM (2 * STG_ELEMS * 2)

__device__ __forceinline__ void mma_bf16(float* d, const uint* a, const uint* bfr) {
    asm("mma.sync.aligned.m16n8k16.row.col.f32.bf16.bf16.f32 "
        "{%0,%1,%2,%3}, {%4,%5,%6,%7}, {%8,%9}, {%0,%1,%2,%3};"
        : "+f"(d[0]), "+f"(d[1]), "+f"(d[2]), "+f"(d[3])
        : "r"(a[0]), "r"(a[1]), "r"(a[2]), "r"(a[3]), "r"(bfr[0]), "r"(bfr[1]));
}

__device__ __forceinline__ void ldsm4(uint* r, uint addr) {
    asm volatile("ldmatrix.sync.aligned.m8n8.x4.shared.b16 {%0,%1,%2,%3}, [%4];"
                 : "=r"(r[0]), "=r"(r[1]), "=r"(r[2]), "=r"(r[3]) : "r"(addr));
}
__device__ __forceinline__ void ldsm4t(uint* r, uint addr) {
    asm volatile("ldmatrix.sync.aligned.m8n8.x4.trans.shared.b16 {%0,%1,%2,%3}, [%4];"
                 : "=r"(r[0]), "=r"(r[1]), "=r"(r[2]), "=r"(r[3]) : "r"(addr));
}

__global__ void __launch_bounds__(256) k_gemm(float* __restrict__ out) {
    extern __shared__ __align__(16) __nv_bfloat16 S[];
    int t = threadIdx.x, warp = t >> 5, lane = t & 31;
    int wm = warp >> 2, wn = warp & 3;
    int mt = blockIdx.x & 7, nt = blockIdx.x >> 3, b = blockIdx.y;

    const __nv_bfloat16* srcA[2] = {
        g_Phi + ((long)b * KK + mt * 64) * NN,
        g_Plo + ((long)b * KK + mt * 64) * NN
    };
    const __nv_bfloat16* srcB[2] = {
        g_hhi + (long)b * NN * CC + nt * 64,
        g_hlo + (long)b * NN * CC + nt * 64
    };

#define COPY(buf, chunk)                                                          \
    {                                                                             \
        _Pragma("unroll")                                                         \
        for (int arr = 0; arr < 2; arr++) {                                       \
            const __nv_bfloat16* sp = srcA[arr] + (chunk) * 64;                   \
            uint dbase = (uint)__cvta_generic_to_shared(                          \
                S + (buf) * STG_ELEMS + arr * ARR);                               \
            _Pragma("unroll")                                                     \
            for (int q = 0; q < 2; q++) {                                         \
                int idx = t + 256 * q;                                            \
                int row = idx >> 3, seg = idx & 7;                                \
                asm volatile("cp.async.cg.shared.global [%0], [%1], 16;"          \
                             :: "r"(dbase + (row * PITCH + seg * 8) * 2),         \
                                "l"(sp + (long)row * NN + seg * 8) : "memory");   \
            }                                                                     \
        }                                                                         \
        _Pragma("unroll")                                                         \
        for (int arr = 0; arr < 2; arr++) {                                       \
            const __nv_bfloat16* sp = srcB[arr] + (long)(chunk) * 64 * CC;        \
            uint dbase = (uint)__cvta_generic_to_shared(                          \
                S + (buf) * STG_ELEMS + (2 + arr) * ARR);                         \
            _Pragma("unroll")                                                     \
            for (int q = 0; q < 2; q++) {                                         \
                int idx = t + 256 * q;                                            \
                int row = idx >> 3, seg = idx & 7;                                \
                asm volatile("cp.async.cg.shared.global [%0], [%1], 16;"          \
                             :: "r"(dbase + (row * PITCH + seg * 8) * 2),         \
                                "l"(sp + (long)row * CC + seg * 8) : "memory");   \
            }                                                                     \
        }                                                                         \
        asm volatile("cp.async.commit_group;" ::: "memory");                      \
    }

    float acc[2][2][4];
#pragma unroll
    for (int fm = 0; fm < 2; fm++)
#pragma unroll
        for (int fn = 0; fn < 2; fn++)
#pragma unroll
            for (int q = 0; q < 4; q++) acc[fm][fn][q] = 0.f;

    COPY(0, 0)

    // fused fill: unselected rows i in [mt*256,+256), cols [nt*64,+64)
    {
        int i = mt * 256 + t;
        if (g_rank[b * NN + i] >= KK) {
            float* ob = out + (long)b * CC * NN + i;
            const float* hpb = g_hp + b * CC + nt * 64;
#pragma unroll 8
            for (int c = 0; c < 64; c++)
                ob[(long)(nt * 64 + c) * NN] = hpb[c];
        }
    }

    int lg = lane & 15, lh = lane >> 4;

    for (int c = 0; c < 32; c++) {
        if (c + 1 < 32) {
            COPY((c + 1) & 1, c + 1)
            asm volatile("cp.async.wait_group 1;" ::: "memory");
        } else {
            asm volatile("cp.async.wait_group 0;" ::: "memory");
        }
        __syncthreads();

        uint Sb = (uint)__cvta_generic_to_shared(S + (c & 1) * STG_ELEMS);
        uint sAhi = Sb, sAlo = Sb + ARR * 2, sBhi = Sb + 2 * ARR * 2, sBlo = Sb + 3 * ARR * 2;

#pragma unroll
        for (int ks = 0; ks < 4; ks++) {
            int k0 = ks * 16;
            uint ahi[2][4], alo[2][4], bhi[4], blo[4];
#pragma unroll
            for (int fm = 0; fm < 2; fm++) {
                uint ra = (uint)((wm * 32 + fm * 16 + lg) * PITCH + k0 + lh * 8) * 2;
                ldsm4(ahi[fm], sAhi + ra);
                ldsm4(alo[fm], sAlo + ra);
            }
            uint rb = (uint)((k0 + lg) * PITCH + wn * 16 + lh * 8) * 2;
            ldsm4t(bhi, sBhi + rb);
            ldsm4t(blo, sBlo + rb);

#pragma unroll
            for (int fm = 0; fm < 2; fm++)
#pragma unroll
                for (int fn = 0; fn < 2; fn++) {
                    mma_bf16(acc[fm][fn], ahi[fm], bhi + 2 * fn);
                    mma_bf16(acc[fm][fn], ahi[fm], blo + 2 * fn);
                    mma_bf16(acc[fm][fn], alo[fm], bhi + 2 * fn);
                }
        }
        __syncthreads();
    }
#undef COPY

    int g = lane >> 2, tig = lane & 3;
    float* ob = out + (long)b * CC * NN;
#pragma unroll
    for (int fm = 0; fm < 2; fm++) {
        int slot0 = mt * 64 + wm * 32 + fm * 16 + g;
        int i0 = g_sel[b * KK + slot0];
        int i1 = g_sel[b * KK + slot0 + 8];
        float2 za = ((const float2*)g_Z2)[b * KK + slot0];
        float2 zb = ((const float2*)g_Z2)[b * KK + slot0 + 8];
        float z0 = 1.f / (za.x + za.y);
        float z1 = 1.f / (zb.x + zb.y);
#pragma unroll
        for (int fn = 0; fn < 2; fn++) {
            int c0 = nt * 64 + wn * 16 + fn * 8 + 2 * tig;
            ob[(long)(c0)     * NN + i0] = fmaxf(acc[fm][fn][0] * z0, 0.f);
            ob[(long)(c0 + 1) * NN + i0] = fmaxf(acc[fm][fn][1] * z0, 0.f);
            ob[(long)(c0)     * NN + i1] = fmaxf(acc[fm][fn][2] * z1, 0.f);
            ob[(long)(c0 + 1) * NN + i1] = fmaxf(acc[fm][fn][3] * z1, 0.f);
        }
    }
}

// ---------------------------------------------------------------------------
extern "C" void kernel_launch(void* const* d_in, const int* in_sizes, int n_in,
                              void* d_out, int out_size) {
    const float* x = nullptr;
    const float* W = nullptr;
    const float* a = nullptr;
    for (int k = 0; k < n_in; k++) {
        if (in_sizes[k] == BB * NN * CC)      x = (const float*)d_in[k];
        else if (in_sizes[k] == CC * CC)      W = (const float*)d_in[k];
        else if (in_sizes[k] == 2 * CC)       a = (const float*)d_in[k];
    }
    float* out = (float*)d_out;

    static int smem_set = 0;
    if (!smem_set) {
        cudaFuncSetAttribute(k_gemm, cudaFuncAttributeMaxDynamicSharedMemorySize, GEMM_SMEM);
        smem_set = 1;
    }

    k_wp   <<<32, 256>>>(W);
    k_h    <<<BB * NN / 32, 128>>>(x, a);
    k_rank <<<dim3(2, 8, BB), 256>>>();
    k_sel  <<<dim3(2, BB), 256>>>(W);
    k_P    <<<dim3(128, BB), 256>>>();
    k_gemm <<<dim3(16, BB), 256, GEMM_SMEM>>>(out);
}